// round 1
// baseline (speedup 1.0000x reference)
#include <cuda_runtime.h>

// Problem constants
#define N_ROIS 256
#define CCH    256
#define HH     25
#define WW     25
#define BIMG   8
#define KIN    12544   // 256*49
#define DFC    1024
#define FCC    512
#define SSC    (25.0f/255.0f)

typedef unsigned long long ull;

// ---------------- scratch (static device globals; no allocs) ----------------
__device__ __align__(256) float g_xt[BIMG*HH*WW*CCH];   // NHWC feature map
__device__ __align__(256) float g_p [N_ROIS*KIN];       // pooled features [n][c*49+bin]
__device__ __align__(256) float g_h1[N_ROIS*DFC];
__device__ __align__(256) float g_h2[N_ROIS*DFC];
__device__ __align__(256) float g_f1[N_ROIS*FCC];
__device__ __align__(256) float g_f2[N_ROIS*FCC];
__device__ __align__(256) float g_off[N_ROIS*98];
__device__ __align__(256) float g_part[2*1024*1024];    // split-K partials (max 2M floats)

// ---------------- f32x2 packed-FMA helpers (Blackwell FFMA2) ----------------
__device__ __forceinline__ ull pkdup(float x){
    ull r; asm("mov.b64 %0, {%1, %1};" : "=l"(r) : "f"(x)); return r;
}
__device__ __forceinline__ void fma2(ull& c, ull a, ull b){
    asm("fma.rn.f32x2 %0, %1, %2, %0;" : "+l"(c) : "l"(a), "l"(b));
}
__device__ __forceinline__ float2 upk(ull v){
    float2 f; asm("mov.b64 {%0, %1}, %2;" : "=f"(f.x), "=f"(f.y) : "l"(v)); return f;
}

// ---------------- NCHW -> NHWC transpose (x is tiny: 2.5 MB) ----------------
__global__ void nchw2nhwc(const float* __restrict__ x){
    int pidx = blockIdx.x;            // b*625 + hw
    int c    = threadIdx.x;
    int b  = pidx / (HH*WW);
    int hw = pidx - b*(HH*WW);
    g_xt[(b*(HH*WW) + hw)*CCH + c] = x[(b*CCH + c)*(HH*WW) + hw];
}

// ---------------- deformable ROI pool ----------------
// One block per (roi, channel-half). 256 threads: 32 channel-groups(float4) x 8 bin-lanes.
// Positions are warp-uniform; channel gathers are 512B coalesced per warp and hit
// L1 after first touch (roi footprint <= ~196KB).
__global__ void __launch_bounds__(256) pool_kernel(const float* __restrict__ rois, int use_off){
    int n    = blockIdx.x;
    int half = blockIdx.y;
    int tid  = threadIdx.x;
    int cg   = ((tid & 31) << 2) + half*128;   // channel base (float4)
    int bs   = tid >> 5;                        // 0..7 bin sub-lane (warp-uniform)

    const float* r = rois + n*5;
    int   b  = (int)r[0];
    float sw = rintf(r[1])*SSC - 0.5f;
    float sh = rintf(r[2])*SSC - 0.5f;
    float rw = fmaxf((rintf(r[3]) + 1.0f)*SSC - 0.5f - sw, 0.1f);
    float rh = fmaxf((rintf(r[4]) + 1.0f)*SSC - 0.5f - sh, 0.1f);
    float bw = rw / 7.0f, bh = rh / 7.0f;
    float bwq = bw*0.25f, bhq = bh*0.25f;

    for(int bin = bs; bin < 49; bin += 8){
        int ph = bin / 7, pw = bin - ph*7;
        float tx = use_off ? g_off[n*98 + bin]      * 0.1f : 0.0f;
        float ty = use_off ? g_off[n*98 + 49 + bin] * 0.1f : 0.0f;
        float wst = pw*bw + sw + tx*rw;
        float hst = ph*bh + sh + ty*rh;

        float ax=0.f, ay=0.f, az=0.f, aw=0.f;
        int cnt = 0;
        #pragma unroll
        for(int iy=0; iy<4; iy++){
            float sy = hst + iy*bhq;
            bool  vy = (sy >= -0.5f) && (sy <= (float)HH - 0.5f);
            float yc  = fminf(fmaxf(sy, 0.0f), (float)(HH-1));
            float y0f = floorf(yc);
            float dy  = yc - y0f;
            int yi0 = (int)y0f;
            int yi1 = (int)ceilf(yc);
            #pragma unroll
            for(int ix=0; ix<4; ix++){
                float sx = wst + ix*bwq;
                if(!vy || sx < -0.5f || sx > (float)WW - 0.5f) continue;
                cnt++;
                float xc  = fminf(fmaxf(sx, 0.0f), (float)(WW-1));
                float x0f = floorf(xc);
                float dx  = xc - x0f;
                int xi0 = (int)x0f;
                int xi1 = (int)ceilf(xc);
                int rb0 = (b*HH + yi0)*WW;
                int rb1 = (b*HH + yi1)*WW;
                float4 v00 = *(const float4*)(g_xt + (rb0 + xi0)*CCH + cg);
                float4 v01 = *(const float4*)(g_xt + (rb0 + xi1)*CCH + cg);
                float4 v10 = *(const float4*)(g_xt + (rb1 + xi0)*CCH + cg);
                float4 v11 = *(const float4*)(g_xt + (rb1 + xi1)*CCH + cg);
                float w00 = (1.f-dx)*(1.f-dy), w01 = dx*(1.f-dy);
                float w10 = (1.f-dx)*dy,       w11 = dx*dy;
                ax += w00*v00.x + w01*v01.x + w10*v10.x + w11*v11.x;
                ay += w00*v00.y + w01*v01.y + w10*v10.y + w11*v11.y;
                az += w00*v00.z + w01*v01.z + w10*v10.z + w11*v11.z;
                aw += w00*v00.w + w01*v01.w + w10*v10.w + w11*v11.w;
            }
        }
        float inv = 1.0f / fmaxf((float)cnt, 1.0f);
        float* pb = g_p + n*KIN + cg*49 + bin;     // layout matches reshape: c*49 + bin
        pb[0]   = ax*inv;
        pb[49]  = ay*inv;
        pb[98]  = az*inv;
        pb[147] = aw*inv;
    }
}

// ---------------- fp32 split-K GEMM: Out_partial[z] = A[64-tile] * W^T[64-tile] ----------------
// BM=BJ=64, BK=16, 256 threads, 4x4 micro-tile using packed f32x2 FMAs (2 FMA/instr).
// A selected from scratch buffers (asel: 0=g_p, 1=g_h1, 2=g_f1). Writes g_part[z][m][j].
__global__ void __launch_bounds__(256) gemm_splitk(int asel, const float* __restrict__ Wt,
                                                  int K, int J, int kslice){
    const float* A = (asel==0) ? g_p : (asel==1 ? g_h1 : g_f1);
    __shared__ float As[16][64];
    __shared__ float Ws[16][64];
    int jt = blockIdx.x << 6;
    int mt = blockIdx.y << 6;
    int z  = blockIdx.z;
    int tid = threadIdx.x;
    int lr = tid >> 2, lc = (tid & 3) << 2;        // loader mapping
    int tj = (tid & 15) << 2, tm = (tid >> 4) << 2; // compute mapping

    const float* Ap = A  + (size_t)(mt + lr)*K + (size_t)z*kslice + lc;
    const float* Wp = Wt + (size_t)(jt + lr)*K + (size_t)z*kslice + lc;

    ull acc[4][2];
    #pragma unroll
    for(int i=0;i<4;i++){ acc[i][0] = 0ull; acc[i][1] = 0ull; }

    for(int kk = 0; kk < kslice; kk += 16){
        float4 av = *(const float4*)(Ap + kk);
        float4 wv = *(const float4*)(Wp + kk);
        As[lc+0][lr]=av.x; As[lc+1][lr]=av.y; As[lc+2][lr]=av.z; As[lc+3][lr]=av.w;
        Ws[lc+0][lr]=wv.x; Ws[lc+1][lr]=wv.y; Ws[lc+2][lr]=wv.z; Ws[lc+3][lr]=wv.w;
        __syncthreads();
        #pragma unroll
        for(int k=0;k<16;k++){
            float4 a = *(const float4*)&As[k][tm];
            ull b01 = *(const ull*)&Ws[k][tj];
            ull b23 = *(const ull*)&Ws[k][tj+2];
            ull a0 = pkdup(a.x), a1 = pkdup(a.y), a2 = pkdup(a.z), a3 = pkdup(a.w);
            fma2(acc[0][0], a0, b01); fma2(acc[0][1], a0, b23);
            fma2(acc[1][0], a1, b01); fma2(acc[1][1], a1, b23);
            fma2(acc[2][0], a2, b01); fma2(acc[2][1], a2, b23);
            fma2(acc[3][0], a3, b01); fma2(acc[3][1], a3, b23);
        }
        __syncthreads();
    }
    #pragma unroll
    for(int i=0;i<4;i++){
        float2 lo = upk(acc[i][0]);
        float2 hi = upk(acc[i][1]);
        float4 o = make_float4(lo.x, lo.y, hi.x, hi.y);
        *(float4*)(g_part + (size_t)(z*N_ROIS + mt + tm + i)*J + jt + tj) = o;
    }
}

// ---------------- split-K reduction + bias + optional relu ----------------
__global__ void reduce_bias_relu(int osel, const float* __restrict__ bias,
                                 int MJ, int J, int SK, int relu){
    int i = blockIdx.x*256 + threadIdx.x;
    if(i >= MJ) return;
    float s = 0.f;
    for(int zz=0; zz<SK; zz++) s += g_part[(size_t)zz*MJ + i];
    s += bias[i % J];
    if(relu) s = fmaxf(s, 0.f);
    float* O = (osel==0) ? g_h1 : (osel==1) ? g_h2 : (osel==2) ? g_f1 : g_f2;
    O[i] = s;
}

// ---------------- small-J GEMM (per-row warp dots): off head & box head ----------------
__global__ void smalldot(int asel, const float* __restrict__ Wt, const float* __restrict__ bias,
                         float* outp, int K, int J){
    const float* A = (asel==0) ? g_h2 : g_f2;
    float* O = outp ? outp : g_off;
    int m    = blockIdx.x;
    int warp = threadIdx.x >> 5;
    int lane = threadIdx.x & 31;
    const float* a = A + (size_t)m*K;
    for(int j = warp; j < J; j += 8){
        const float* w = Wt + (size_t)j*K;
        float s = 0.f;
        for(int k = lane; k < K; k += 32) s += a[k]*w[k];
        #pragma unroll
        for(int o=16; o; o>>=1) s += __shfl_xor_sync(0xffffffffu, s, o);
        if(lane == 0) O[m*J + j] = s + bias[j];
    }
}

// ---------------- launch ----------------
extern "C" void kernel_launch(void* const* d_in, const int* in_sizes, int n_in,
                              void* d_out, int out_size){
    const float* x    = (const float*)d_in[0];
    const float* rois = (const float*)d_in[1];
    const float* ow1  = (const float*)d_in[2];
    const float* ob1  = (const float*)d_in[3];
    const float* ow2  = (const float*)d_in[4];
    const float* ob2  = (const float*)d_in[5];
    const float* ow3  = (const float*)d_in[6];
    const float* ob3  = (const float*)d_in[7];
    const float* f1w  = (const float*)d_in[8];
    const float* f1b  = (const float*)d_in[9];
    const float* f2w  = (const float*)d_in[10];
    const float* f2b  = (const float*)d_in[11];
    const float* bxw  = (const float*)d_in[12];
    const float* bxb  = (const float*)d_in[13];

    // NHWC layout for channel-coalesced gathers
    nchw2nhwc<<<BIMG*HH*WW, CCH>>>(x);

    // pool with zero offsets -> g_p
    pool_kernel<<<dim3(N_ROIS,2), 256>>>(rois, 0);

    // offset branch: h1 = relu(p @ ow1^T + b1)   [256 x 1024], K=12544, SK=8
    gemm_splitk<<<dim3(16,4,8), 256>>>(0, ow1, KIN, DFC, KIN/8);
    reduce_bias_relu<<<(N_ROIS*DFC)/256, 256>>>(0, ob1, N_ROIS*DFC, DFC, 8, 1);

    // h2 = relu(h1 @ ow2^T + b2)   K=1024, SK=8
    gemm_splitk<<<dim3(16,4,8), 256>>>(1, ow2, DFC, DFC, DFC/8);
    reduce_bias_relu<<<(N_ROIS*DFC)/256, 256>>>(1, ob2, N_ROIS*DFC, DFC, 8, 1);

    // off = h2 @ ow3^T + b3   [256 x 98] -> g_off
    smalldot<<<N_ROIS, 256>>>(0, ow3, ob3, nullptr, DFC, 98);

    // pool with learned offsets -> g_p (overwrite)
    pool_kernel<<<dim3(N_ROIS,2), 256>>>(rois, 1);

    // f1 = relu(p @ f1w^T + b)   [256 x 512], K=12544, SK=16
    gemm_splitk<<<dim3(8,4,16), 256>>>(0, f1w, KIN, FCC, KIN/16);
    reduce_bias_relu<<<(N_ROIS*FCC)/256, 256>>>(2, f1b, N_ROIS*FCC, FCC, 16, 1);

    // f2 = relu(f1 @ f2w^T + b)  K=512, SK=16
    gemm_splitk<<<dim3(8,4,16), 256>>>(2, f2w, FCC, FCC, FCC/16);
    reduce_bias_relu<<<(N_ROIS*FCC)/256, 256>>>(3, f2b, N_ROIS*FCC, FCC, 16, 1);

    // out = f2 @ box_w^T + box_b   [256 x 4] -> d_out
    smalldot<<<N_ROIS, 256>>>(1, bxw, bxb, (float*)d_out, FCC, 4);
}

// round 9
// speedup vs baseline: 1.2821x; 1.2821x over previous
#include <cuda_runtime.h>
#include <cuda_bf16.h>
#include <cstdint>

// Problem constants
#define N_ROIS 256
#define CCH    256
#define HH     25
#define WW     25
#define BIMG   8
#define KIN    12544   // 256*49
#define DFC    1024
#define FCC    512
#define SSC    (25.0f/255.0f)

// ---------------- scratch (static device globals; no allocs) ----------------
__device__ __align__(256) float g_xt[BIMG*HH*WW*CCH];        // NHWC feature map
__device__ __align__(256) __nv_bfloat16 g_pa_hi[N_ROIS*KIN];
__device__ __align__(256) __nv_bfloat16 g_pa_lo[N_ROIS*KIN];
__device__ __align__(256) __nv_bfloat16 g_h1hi[N_ROIS*DFC];
__device__ __align__(256) __nv_bfloat16 g_h1lo[N_ROIS*DFC];
__device__ __align__(256) float g_h2[N_ROIS*DFC];
__device__ __align__(256) __nv_bfloat16 g_f1hi[N_ROIS*FCC];
__device__ __align__(256) __nv_bfloat16 g_f1lo[N_ROIS*FCC];
__device__ __align__(256) float g_f2[N_ROIS*FCC];
__device__ __align__(256) float g_off[N_ROIS*98];
__device__ __align__(256) float g_part[5*1024*1024];
// converted weights (hi/lo bf16)
__device__ __align__(256) __nv_bfloat16 g_w1hi [DFC*KIN];
__device__ __align__(256) __nv_bfloat16 g_w1lo [DFC*KIN];
__device__ __align__(256) __nv_bfloat16 g_w2hi [DFC*DFC];
__device__ __align__(256) __nv_bfloat16 g_w2lo [DFC*DFC];
__device__ __align__(256) __nv_bfloat16 g_fw1hi[FCC*KIN];
__device__ __align__(256) __nv_bfloat16 g_fw1lo[FCC*KIN];
__device__ __align__(256) __nv_bfloat16 g_fw2hi[FCC*FCC];
__device__ __align__(256) __nv_bfloat16 g_fw2lo[FCC*FCC];

// ---------------- helpers ----------------
__device__ __forceinline__ uint32_t smem_u32(const void* p){
    uint32_t a;
    asm("{ .reg .u64 t; cvta.to.shared.u64 t, %1; cvt.u32.u64 %0, t; }" : "=r"(a) : "l"(p));
    return a;
}
#define CP_ASYNC16(dst, src) \
    asm volatile("cp.async.cg.shared.global [%0], [%1], 16;" :: "r"(dst), "l"(src) : "memory")
#define CP_COMMIT() asm volatile("cp.async.commit_group;" ::: "memory")
#define CP_WAIT1()  asm volatile("cp.async.wait_group 1;" ::: "memory")
#define CP_WAIT0()  asm volatile("cp.async.wait_group 0;" ::: "memory")

__device__ __forceinline__ void ldm_x4(uint32_t& r0, uint32_t& r1, uint32_t& r2, uint32_t& r3,
                                       uint32_t addr){
    asm volatile("ldmatrix.sync.aligned.m8n8.x4.shared.b16 {%0,%1,%2,%3}, [%4];"
                 : "=r"(r0), "=r"(r1), "=r"(r2), "=r"(r3) : "r"(addr));
}
__device__ __forceinline__ void mma16816(float* c, uint32_t a0, uint32_t a1, uint32_t a2,
                                         uint32_t a3, uint32_t b0, uint32_t b1){
    asm volatile("mma.sync.aligned.m16n8k16.row.col.f32.bf16.bf16.f32 "
                 "{%0,%1,%2,%3}, {%4,%5,%6,%7}, {%8,%9}, {%0,%1,%2,%3};"
                 : "+f"(c[0]), "+f"(c[1]), "+f"(c[2]), "+f"(c[3])
                 : "r"(a0), "r"(a1), "r"(a2), "r"(a3), "r"(b0), "r"(b1));
}

// ---------------- NCHW -> NHWC transpose ----------------
__global__ void nchw2nhwc(const float* __restrict__ x){
    int pidx = blockIdx.x;
    int c    = threadIdx.x;
    int b  = pidx / (HH*WW);
    int hw = pidx - b*(HH*WW);
    g_xt[(b*(HH*WW) + hw)*CCH + c] = x[(b*CCH + c)*(HH*WW) + hw];
}

// ---------------- fp32 -> hi/lo bf16 weight conversion ----------------
__global__ void convw(const float* __restrict__ s, __nv_bfloat16* __restrict__ hi,
                      __nv_bfloat16* __restrict__ lo, int n4){
    int i = blockIdx.x*256 + threadIdx.x;
    if (i >= n4) return;
    float4 v = ((const float4*)s)[i];
    __nv_bfloat16 h0 = __float2bfloat16(v.x), h1 = __float2bfloat16(v.y);
    __nv_bfloat16 h2 = __float2bfloat16(v.z), h3 = __float2bfloat16(v.w);
    __nv_bfloat16 l0 = __float2bfloat16(v.x - __bfloat162float(h0));
    __nv_bfloat16 l1 = __float2bfloat16(v.y - __bfloat162float(h1));
    __nv_bfloat16 l2 = __float2bfloat16(v.z - __bfloat162float(h2));
    __nv_bfloat16 l3 = __float2bfloat16(v.w - __bfloat162float(h3));
    ushort4 hv = make_ushort4(*(unsigned short*)&h0, *(unsigned short*)&h1,
                              *(unsigned short*)&h2, *(unsigned short*)&h3);
    ushort4 lv = make_ushort4(*(unsigned short*)&l0, *(unsigned short*)&l1,
                              *(unsigned short*)&l2, *(unsigned short*)&l3);
    ((ushort4*)hi)[i] = hv;
    ((ushort4*)lo)[i] = lv;
}

// ---------------- deformable ROI pool (writes hi/lo bf16 pooled features) ----------------
__global__ void __launch_bounds__(256) pool_kernel(const float* __restrict__ rois, int use_off){
    int n    = blockIdx.x;
    int half = blockIdx.y;
    int tid  = threadIdx.x;
    int cg   = ((tid & 31) << 2) + half*128;
    int bs   = tid >> 5;

    const float* r = rois + n*5;
    int   b  = (int)r[0];
    float sw = rintf(r[1])*SSC - 0.5f;
    float sh = rintf(r[2])*SSC - 0.5f;
    float rw = fmaxf((rintf(r[3]) + 1.0f)*SSC - 0.5f - sw, 0.1f);
    float rh = fmaxf((rintf(r[4]) + 1.0f)*SSC - 0.5f - sh, 0.1f);
    float bw = rw / 7.0f, bh = rh / 7.0f;
    float bwq = bw*0.25f, bhq = bh*0.25f;

    for(int bin = bs; bin < 49; bin += 8){
        int ph = bin / 7, pw = bin - ph*7;
        float tx = use_off ? g_off[n*98 + bin]      * 0.1f : 0.0f;
        float ty = use_off ? g_off[n*98 + 49 + bin] * 0.1f : 0.0f;
        float wst = pw*bw + sw + tx*rw;
        float hst = ph*bh + sh + ty*rh;

        float ax=0.f, ay=0.f, az=0.f, aw=0.f;
        int cnt = 0;
        #pragma unroll
        for(int iy=0; iy<4; iy++){
            float sy = hst + iy*bhq;
            bool  vy = (sy >= -0.5f) && (sy <= (float)HH - 0.5f);
            float yc  = fminf(fmaxf(sy, 0.0f), (float)(HH-1));
            float y0f = floorf(yc);
            float dy  = yc - y0f;
            int yi0 = (int)y0f;
            int yi1 = (int)ceilf(yc);
            #pragma unroll
            for(int ix=0; ix<4; ix++){
                float sx = wst + ix*bwq;
                if(!vy || sx < -0.5f || sx > (float)WW - 0.5f) continue;
                cnt++;
                float xc  = fminf(fmaxf(sx, 0.0f), (float)(WW-1));
                float x0f = floorf(xc);
                float dx  = xc - x0f;
                int xi0 = (int)x0f;
                int xi1 = (int)ceilf(xc);
                int rb0 = (b*HH + yi0)*WW;
                int rb1 = (b*HH + yi1)*WW;
                float4 v00 = *(const float4*)(g_xt + (rb0 + xi0)*CCH + cg);
                float4 v01 = *(const float4*)(g_xt + (rb0 + xi1)*CCH + cg);
                float4 v10 = *(const float4*)(g_xt + (rb1 + xi0)*CCH + cg);
                float4 v11 = *(const float4*)(g_xt + (rb1 + xi1)*CCH + cg);
                float w00 = (1.f-dx)*(1.f-dy), w01 = dx*(1.f-dy);
                float w10 = (1.f-dx)*dy,       w11 = dx*dy;
                ax += w00*v00.x + w01*v01.x + w10*v10.x + w11*v11.x;
                ay += w00*v00.y + w01*v01.y + w10*v10.y + w11*v11.y;
                az += w00*v00.z + w01*v01.z + w10*v10.z + w11*v11.z;
                aw += w00*v00.w + w01*v01.w + w10*v10.w + w11*v11.w;
            }
        }
        float inv = 1.0f / fmaxf((float)cnt, 1.0f);
        int idx = n*KIN + cg*49 + bin;   // layout matches reshape: c*49 + bin
        float v0 = ax*inv, v1 = ay*inv, v2 = az*inv, v3 = aw*inv;
        __nv_bfloat16 h;
        h = __float2bfloat16(v0); g_pa_hi[idx]     = h; g_pa_lo[idx]     = __float2bfloat16(v0 - __bfloat162float(h));
        h = __float2bfloat16(v1); g_pa_hi[idx+49]  = h; g_pa_lo[idx+49]  = __float2bfloat16(v1 - __bfloat162float(h));
        h = __float2bfloat16(v2); g_pa_hi[idx+98]  = h; g_pa_lo[idx+98]  = __float2bfloat16(v2 - __bfloat162float(h));
        h = __float2bfloat16(v3); g_pa_hi[idx+147] = h; g_pa_lo[idx+147] = __float2bfloat16(v3 - __bfloat162float(h));
    }
}

// ---------------- bf16 hi/lo split-K GEMM via mma.sync (HMMA) ----------------
// C[m][j] = sum_k A[m][k]*W[j][k]. CTA tile 64x128, BK=32, 8 warps (2x4, 32x32 each).
// 3 passes fused per k16 (AhWh + AhWl + AlWh), fp32 accum. Writes g_part[z].
#define BM 64
#define BN 128
#define BK 32
#define ROWB 80                 // padded row bytes (32 bf16 = 64B + 16B pad)
#define STG_A_HI 0
#define STG_A_LO (BM*ROWB)              // 5120
#define STG_W_HI (2*BM*ROWB)            // 10240
#define STG_W_LO (2*BM*ROWB + BN*ROWB)  // 20480
#define STG_SZ   (2*BM*ROWB + 2*BN*ROWB) // 30720
#define GSMEM    (2*STG_SZ)              // 61440

__global__ void __launch_bounds__(256)
gemm_mma(int asel, const __nv_bfloat16* __restrict__ Whi, const __nv_bfloat16* __restrict__ Wlo,
         int K, int J, int cpz){
    extern __shared__ char smem[];
    uint32_t sb = smem_u32(smem);
    const __nv_bfloat16 *Ahi, *Alo;
    if      (asel == 0){ Ahi = g_pa_hi; Alo = g_pa_lo; }
    else if (asel == 1){ Ahi = g_h1hi;  Alo = g_h1lo;  }
    else               { Ahi = g_f1hi;  Alo = g_f1lo;  }

    int jt  = blockIdx.x*BN;
    int mt  = blockIdx.y*BM;
    int z   = blockIdx.z;
    int tid = threadIdx.x, wid = tid >> 5, lane = tid & 31;
    int wm = wid >> 2, wn = wid & 3;   // warp grid 2 x 4

    // loader mappings
    int arow = tid >> 2, aseg = tid & 3;                 // A: 64 rows x 4 16B-segs
    const char* gAh = (const char*)(Ahi) + ((size_t)(mt + arow)*K + (size_t)aseg*8)*2;
    const char* gAl = (const char*)(Alo) + ((size_t)(mt + arow)*K + (size_t)aseg*8)*2;
    uint32_t dA = sb + arow*ROWB + aseg*16;
    int wrow0 = tid >> 1, wseg0 = (tid & 1) << 1;        // W: 128 rows, segs {wseg0, wseg0+1}
    const char* gWh = (const char*)(Whi) + ((size_t)(jt + wrow0)*K + (size_t)wseg0*8)*2;
    const char* gWl = (const char*)(Wlo) + ((size_t)(jt + wrow0)*K + (size_t)wseg0*8)*2;
    uint32_t dW = sb + wrow0*ROWB + wseg0*16;
    size_t kstep = (size_t)z*cpz*BK*2;                   // byte offset for this z
    gAh += kstep; gAl += kstep; gWh += kstep; gWl += kstep;

    // ldmatrix per-lane addressing (within a stage)
    uint32_t lrow = lane & 15;
    uint32_t lcol = (lane >> 4) << 4;   // 0 or 16 bytes (k-halves)
    uint32_t aA0 = (wm*32 + 0  + lrow)*ROWB + lcol;
    uint32_t aA1 = (wm*32 + 16 + lrow)*ROWB + lcol;
    uint32_t aW0 = (wn*32 + 0  + lrow)*ROWB + lcol;
    uint32_t aW1 = (wn*32 + 16 + lrow)*ROWB + lcol;

    float acc[2][4][4];
    #pragma unroll
    for (int t = 0; t < 2; t++)
        #pragma unroll
        for (int u = 0; u < 4; u++)
            #pragma unroll
            for (int q = 0; q < 4; q++) acc[t][u][q] = 0.f;

    // prologue: load chunk 0 into stage 0
    {
        CP_ASYNC16(dA + STG_A_HI, gAh);
        CP_ASYNC16(dA + STG_A_LO, gAl);
        CP_ASYNC16(dW + STG_W_HI,      gWh);
        CP_ASYNC16(dW + STG_W_HI + 16, gWh + 16);
        CP_ASYNC16(dW + STG_W_LO,      gWl);
        CP_ASYNC16(dW + STG_W_LO + 16, gWl + 16);
        CP_COMMIT();
    }

    for (int c = 0; c < cpz; c++){
        int cs = (c & 1) * STG_SZ;
        // prefetch next chunk into other stage
        if (c + 1 < cpz){
            size_t off = (size_t)(c + 1)*BK*2;
            int ns = ((c + 1) & 1) * STG_SZ;
            CP_ASYNC16(dA + ns + STG_A_HI, gAh + off);
            CP_ASYNC16(dA + ns + STG_A_LO, gAl + off);
            CP_ASYNC16(dW + ns + STG_W_HI,      gWh + off);
            CP_ASYNC16(dW + ns + STG_W_HI + 16, gWh + off + 16);
            CP_ASYNC16(dW + ns + STG_W_LO,      gWl + off);
            CP_ASYNC16(dW + ns + STG_W_LO + 16, gWl + off + 16);
            CP_COMMIT();
            CP_WAIT1();
        } else {
            CP_WAIT0();
        }
        __syncthreads();

        #pragma unroll
        for (int ks = 0; ks < 2; ks++){
            uint32_t kb = cs + ks*32;
            uint32_t ah[2][4], al[2][4], wh[2][4], wl[2][4];
            ldm_x4(ah[0][0], ah[0][1], ah[0][2], ah[0][3], sb + STG_A_HI + kb + aA0);
            ldm_x4(ah[1][0], ah[1][1], ah[1][2], ah[1][3], sb + STG_A_HI + kb + aA1);
            ldm_x4(al[0][0], al[0][1], al[0][2], al[0][3], sb + STG_A_LO + kb + aA0);
            ldm_x4(al[1][0], al[1][1], al[1][2], al[1][3], sb + STG_A_LO + kb + aA1);
            ldm_x4(wh[0][0], wh[0][1], wh[0][2], wh[0][3], sb + STG_W_HI + kb + aW0);
            ldm_x4(wh[1][0], wh[1][1], wh[1][2], wh[1][3], sb + STG_W_HI + kb + aW1);
            ldm_x4(wl[0][0], wl[0][1], wl[0][2], wl[0][3], sb + STG_W_LO + kb + aW0);
            ldm_x4(wl[1][0], wl[1][1], wl[1][2], wl[1][3], sb + STG_W_LO + kb + aW1);
            // n8-tile u: pair p = u>>1, regs {r[u&1], r[(u&1)+2]}
            #pragma unroll
            for (int t = 0; t < 2; t++){
                #pragma unroll
                for (int u = 0; u < 4; u++){
                    int p = u >> 1, s = u & 1;
                    uint32_t bh0 = wh[p][s], bh1 = wh[p][s+2];
                    uint32_t bl0 = wl[p][s], bl1 = wl[p][s+2];
                    mma16816(acc[t][u], ah[t][0], ah[t][1], ah[t][2], ah[t][3], bh0, bh1);
                    mma16816(acc[t][u], ah[t][0], ah[t][1], ah[t][2], ah[t][3], bl0, bl1);
                    mma16816(acc[t][u], al[t][0], al[t][1], al[t][2], al[t][3], bh0, bh1);
                }
            }
        }
        __syncthreads();
    }

    // epilogue: write split-K partials
    int gmb = mt + wm*32;
    int gjb = jt + wn*32;
    int r0 = lane >> 2, c0 = (lane & 3) << 1;
    #pragma unroll
    for (int t = 0; t < 2; t++){
        #pragma unroll
        for (int u = 0; u < 4; u++){
            int gm = gmb + t*16 + r0;
            int gj = gjb + u*8 + c0;
            float2 lo = make_float2(acc[t][u][0], acc[t][u][1]);
            float2 hi = make_float2(acc[t][u][2], acc[t][u][3]);
            *(float2*)(g_part + ((size_t)z*N_ROIS + gm    )*J + gj) = lo;
            *(float2*)(g_part + ((size_t)z*N_ROIS + gm + 8)*J + gj) = hi;
        }
    }
}

// ---------------- split-K reduction + bias + relu (+ hi/lo conversion) ----------------
__global__ void reduce_bias_relu(int osel, const float* __restrict__ bias, int MJ, int J, int SK){
    int i = blockIdx.x*256 + threadIdx.x;
    if (i >= MJ) return;
    float s = 0.f;
    for (int zz = 0; zz < SK; zz++) s += g_part[(size_t)zz*MJ + i];
    s += bias[i % J];
    s = fmaxf(s, 0.f);
    if (osel == 0){
        __nv_bfloat16 h = __float2bfloat16(s);
        g_h1hi[i] = h; g_h1lo[i] = __float2bfloat16(s - __bfloat162float(h));
    } else if (osel == 1){
        g_h2[i] = s;
    } else if (osel == 2){
        __nv_bfloat16 h = __float2bfloat16(s);
        g_f1hi[i] = h; g_f1lo[i] = __float2bfloat16(s - __bfloat162float(h));
    } else {
        g_f2[i] = s;
    }
}

// ---------------- small-J heads (fp32 warp dots) ----------------
__global__ void smalldot(int asel, const float* __restrict__ Wt, const float* __restrict__ bias,
                         float* outp, int K, int J){
    const float* A = (asel == 0) ? g_h2 : g_f2;
    float* O = outp ? outp : g_off;
    int m    = blockIdx.x;
    int warp = threadIdx.x >> 5;
    int lane = threadIdx.x & 31;
    const float* a = A + (size_t)m*K;
    for (int j = warp; j < J; j += 8){
        const float* w = Wt + (size_t)j*K;
        float s = 0.f;
        for (int k = lane; k < K; k += 32) s += a[k]*w[k];
        #pragma unroll
        for (int o = 16; o; o >>= 1) s += __shfl_xor_sync(0xffffffffu, s, o);
        if (lane == 0) O[m*J + j] = s + bias[j];
    }
}

// ---------------- launch ----------------
extern "C" void kernel_launch(void* const* d_in, const int* in_sizes, int n_in,
                              void* d_out, int out_size){
    const float* x    = (const float*)d_in[0];
    const float* rois = (const float*)d_in[1];
    const float* ow1  = (const float*)d_in[2];
    const float* ob1  = (const float*)d_in[3];
    const float* ow2  = (const float*)d_in[4];
    const float* ob2  = (const float*)d_in[5];
    const float* ow3  = (const float*)d_in[6];
    const float* ob3  = (const float*)d_in[7];
    const float* f1w  = (const float*)d_in[8];
    const float* f1b  = (const float*)d_in[9];
    const float* f2w  = (const float*)d_in[10];
    const float* f2b  = (const float*)d_in[11];
    const float* bxw  = (const float*)d_in[12];
    const float* bxb  = (const float*)d_in[13];

    cudaFuncSetAttribute(gemm_mma, cudaFuncAttributeMaxDynamicSharedMemorySize, GSMEM);

    __nv_bfloat16 *w1hi, *w1lo, *w2hi, *w2lo, *fw1hi, *fw1lo, *fw2hi, *fw2lo;
    cudaGetSymbolAddress((void**)&w1hi,  g_w1hi);  cudaGetSymbolAddress((void**)&w1lo,  g_w1lo);
    cudaGetSymbolAddress((void**)&w2hi,  g_w2hi);  cudaGetSymbolAddress((void**)&w2lo,  g_w2lo);
    cudaGetSymbolAddress((void**)&fw1hi, g_fw1hi); cudaGetSymbolAddress((void**)&fw1lo, g_fw1lo);
    cudaGetSymbolAddress((void**)&fw2hi, g_fw2hi); cudaGetSymbolAddress((void**)&fw2lo, g_fw2lo);

    nchw2nhwc<<<BIMG*HH*WW, CCH>>>(x);

    convw<<<(DFC*KIN/4 + 255)/256, 256>>>(ow1, w1hi, w1lo, DFC*KIN/4);
    convw<<<(DFC*DFC/4 + 255)/256, 256>>>(ow2, w2hi, w2lo, DFC*DFC/4);
    convw<<<(FCC*KIN/4 + 255)/256, 256>>>(f1w, fw1hi, fw1lo, FCC*KIN/4);
    convw<<<(FCC*FCC/4 + 255)/256, 256>>>(f2w, fw2hi, fw2lo, FCC*FCC/4);

    pool_kernel<<<dim3(N_ROIS,2), 256>>>(rois, 0);

    // h1 = relu(p @ ow1^T + b1)  [256x1024], K=12544: SK=4, cpz=98
    gemm_mma<<<dim3(8,4,4), 256, GSMEM>>>(0, w1hi, w1lo, KIN, DFC, 98);
    reduce_bias_relu<<<(N_ROIS*DFC)/256, 256>>>(0, ob1, N_ROIS*DFC, DFC, 4);

    // h2 = relu(h1 @ ow2^T + b2)  K=1024: SK=4, cpz=8
    gemm_mma<<<dim3(8,4,4), 256, GSMEM>>>(1, w2hi, w2lo, DFC, DFC, 8);
    reduce_bias_relu<<<(N_ROIS*DFC)/256, 256>>>(1, ob2, N_ROIS*DFC, DFC, 4);

    // off = h2 @ ow3^T + b3  [256x98]
    smalldot<<<N_ROIS, 256>>>(0, ow3, ob3, nullptr, DFC, 98);

    pool_kernel<<<dim3(N_ROIS,2), 256>>>(rois, 1);

    // f1 = relu(p @ f1w^T + b)  [256x512], K=12544: SK=8, cpz=49
    gemm_mma<<<dim3(4,4,8), 256, GSMEM>>>(0, fw1hi, fw1lo, KIN, FCC, 49);
    reduce_bias_relu<<<(N_ROIS*FCC)/256, 256>>>(2, f1b, N_ROIS*FCC, FCC, 8);

    // f2 = relu(f1 @ f2w^T + b)  K=512: SK=4, cpz=4
    gemm_mma<<<dim3(4,4,4), 256, GSMEM>>>(2, fw2hi, fw2lo, FCC, FCC, 4);
    reduce_bias_relu<<<(N_ROIS*FCC)/256, 256>>>(3, f2b, N_ROIS*FCC, FCC, 4);

    // out = f2 @ box_w^T + box_b  [256x4]
    smalldot<<<N_ROIS, 256>>>(1, bxw, bxb, (float*)d_out, FCC, 4);
}

// round 11
// speedup vs baseline: 1.3208x; 1.0302x over previous
#include <cuda_runtime.h>
#include <cuda_bf16.h>
#include <cstdint>

// Problem constants
#define N_ROIS 256
#define CCH    256
#define HH     25
#define WW     25
#define BIMG   8
#define KIN    12544   // 256*49
#define DFC    1024
#define FCC    512
#define SSC    (25.0f/255.0f)

// ---------------- scratch (static device globals; no allocs) ----------------
__device__ __align__(256) float g_xt[BIMG*HH*WW*CCH];        // NHWC feature map
__device__ __align__(256) __nv_bfloat16 g_pa_hi[N_ROIS*KIN];
__device__ __align__(256) __nv_bfloat16 g_pa_lo[N_ROIS*KIN];
__device__ __align__(256) __nv_bfloat16 g_h1hi[N_ROIS*DFC];
__device__ __align__(256) __nv_bfloat16 g_h1lo[N_ROIS*DFC];
__device__ __align__(256) float g_h2[N_ROIS*DFC];
__device__ __align__(256) __nv_bfloat16 g_f1hi[N_ROIS*FCC];
__device__ __align__(256) __nv_bfloat16 g_f1lo[N_ROIS*FCC];
__device__ __align__(256) float g_f2[N_ROIS*FCC];
__device__ __align__(256) float g_off[N_ROIS*98];
__device__ __align__(256) float g_part[5*1024*1024];
// converted weights (hi/lo bf16)
__device__ __align__(256) __nv_bfloat16 g_w1hi [DFC*KIN];
__device__ __align__(256) __nv_bfloat16 g_w1lo [DFC*KIN];
__device__ __align__(256) __nv_bfloat16 g_w2hi [DFC*DFC];
__device__ __align__(256) __nv_bfloat16 g_w2lo [DFC*DFC];
__device__ __align__(256) __nv_bfloat16 g_fw1hi[FCC*KIN];
__device__ __align__(256) __nv_bfloat16 g_fw1lo[FCC*KIN];
__device__ __align__(256) __nv_bfloat16 g_fw2hi[FCC*FCC];
__device__ __align__(256) __nv_bfloat16 g_fw2lo[FCC*FCC];

// ---------------- helpers ----------------
__device__ __forceinline__ uint32_t smem_u32(const void* p){
    uint32_t a;
    asm("{ .reg .u64 t; cvta.to.shared.u64 t, %1; cvt.u32.u64 %0, t; }" : "=r"(a) : "l"(p));
    return a;
}
#define CP_ASYNC16(dst, src) \
    asm volatile("cp.async.cg.shared.global [%0], [%1], 16;" :: "r"(dst), "l"(src) : "memory")
#define CP_COMMIT() asm volatile("cp.async.commit_group;" ::: "memory")
#define CP_WAIT1()  asm volatile("cp.async.wait_group 1;" ::: "memory")
#define CP_WAIT0()  asm volatile("cp.async.wait_group 0;" ::: "memory")

__device__ __forceinline__ void ldm_x4(uint32_t& r0, uint32_t& r1, uint32_t& r2, uint32_t& r3,
                                       uint32_t addr){
    asm volatile("ldmatrix.sync.aligned.m8n8.x4.shared.b16 {%0,%1,%2,%3}, [%4];"
                 : "=r"(r0), "=r"(r1), "=r"(r2), "=r"(r3) : "r"(addr));
}
__device__ __forceinline__ void mma16816(float* c, uint32_t a0, uint32_t a1, uint32_t a2,
                                         uint32_t a3, uint32_t b0, uint32_t b1){
    asm volatile("mma.sync.aligned.m16n8k16.row.col.f32.bf16.bf16.f32 "
                 "{%0,%1,%2,%3}, {%4,%5,%6,%7}, {%8,%9}, {%0,%1,%2,%3};"
                 : "+f"(c[0]), "+f"(c[1]), "+f"(c[2]), "+f"(c[3])
                 : "r"(a0), "r"(a1), "r"(a2), "r"(a3), "r"(b0), "r"(b1));
}

// ---------------- NCHW -> NHWC transpose ----------------
__global__ void nchw2nhwc(const float* __restrict__ x){
    int pidx = blockIdx.x;
    int c    = threadIdx.x;
    int b  = pidx / (HH*WW);
    int hw = pidx - b*(HH*WW);
    g_xt[(b*(HH*WW) + hw)*CCH + c] = x[(b*CCH + c)*(HH*WW) + hw];
}

// ---------------- fp32 -> hi/lo bf16 weight conversion ----------------
__global__ void convw(const float* __restrict__ s, __nv_bfloat16* __restrict__ hi,
                      __nv_bfloat16* __restrict__ lo, int n4){
    int i = blockIdx.x*256 + threadIdx.x;
    if (i >= n4) return;
    float4 v = ((const float4*)s)[i];
    __nv_bfloat16 h0 = __float2bfloat16(v.x), h1 = __float2bfloat16(v.y);
    __nv_bfloat16 h2 = __float2bfloat16(v.z), h3 = __float2bfloat16(v.w);
    __nv_bfloat16 l0 = __float2bfloat16(v.x - __bfloat162float(h0));
    __nv_bfloat16 l1 = __float2bfloat16(v.y - __bfloat162float(h1));
    __nv_bfloat16 l2 = __float2bfloat16(v.z - __bfloat162float(h2));
    __nv_bfloat16 l3 = __float2bfloat16(v.w - __bfloat162float(h3));
    ushort4 hv = make_ushort4(*(unsigned short*)&h0, *(unsigned short*)&h1,
                              *(unsigned short*)&h2, *(unsigned short*)&h3);
    ushort4 lv = make_ushort4(*(unsigned short*)&l0, *(unsigned short*)&l1,
                              *(unsigned short*)&l2, *(unsigned short*)&l3);
    ((ushort4*)hi)[i] = hv;
    ((ushort4*)lo)[i] = lv;
}

// ---------------- deformable ROI pool (writes hi/lo bf16 pooled features) ----------------
__global__ void __launch_bounds__(256) pool_kernel(const float* __restrict__ rois, int use_off){
    int n    = blockIdx.x;
    int half = blockIdx.y;
    int tid  = threadIdx.x;
    int cg   = ((tid & 31) << 2) + half*128;
    int bs   = tid >> 5;

    const float* r = rois + n*5;
    int   b  = (int)r[0];
    float sw = rintf(r[1])*SSC - 0.5f;
    float sh = rintf(r[2])*SSC - 0.5f;
    float rw = fmaxf((rintf(r[3]) + 1.0f)*SSC - 0.5f - sw, 0.1f);
    float rh = fmaxf((rintf(r[4]) + 1.0f)*SSC - 0.5f - sh, 0.1f);
    float bw = rw / 7.0f, bh = rh / 7.0f;
    float bwq = bw*0.25f, bhq = bh*0.25f;

    for(int bin = bs; bin < 49; bin += 8){
        int ph = bin / 7, pw = bin - ph*7;
        float tx = use_off ? g_off[n*98 + bin]      * 0.1f : 0.0f;
        float ty = use_off ? g_off[n*98 + 49 + bin] * 0.1f : 0.0f;
        float wst = pw*bw + sw + tx*rw;
        float hst = ph*bh + sh + ty*rh;

        float ax=0.f, ay=0.f, az=0.f, aw=0.f;
        int cnt = 0;
        #pragma unroll
        for(int iy=0; iy<4; iy++){
            float sy = hst + iy*bhq;
            bool  vy = (sy >= -0.5f) && (sy <= (float)HH - 0.5f);
            float yc  = fminf(fmaxf(sy, 0.0f), (float)(HH-1));
            float y0f = floorf(yc);
            float dy  = yc - y0f;
            int yi0 = (int)y0f;
            int yi1 = (int)ceilf(yc);
            #pragma unroll
            for(int ix=0; ix<4; ix++){
                float sx = wst + ix*bwq;
                if(!vy || sx < -0.5f || sx > (float)WW - 0.5f) continue;
                cnt++;
                float xc  = fminf(fmaxf(sx, 0.0f), (float)(WW-1));
                float x0f = floorf(xc);
                float dx  = xc - x0f;
                int xi0 = (int)x0f;
                int xi1 = (int)ceilf(xc);
                int rb0 = (b*HH + yi0)*WW;
                int rb1 = (b*HH + yi1)*WW;
                float4 v00 = *(const float4*)(g_xt + (rb0 + xi0)*CCH + cg);
                float4 v01 = *(const float4*)(g_xt + (rb0 + xi1)*CCH + cg);
                float4 v10 = *(const float4*)(g_xt + (rb1 + xi0)*CCH + cg);
                float4 v11 = *(const float4*)(g_xt + (rb1 + xi1)*CCH + cg);
                float w00 = (1.f-dx)*(1.f-dy), w01 = dx*(1.f-dy);
                float w10 = (1.f-dx)*dy,       w11 = dx*dy;
                ax += w00*v00.x + w01*v01.x + w10*v10.x + w11*v11.x;
                ay += w00*v00.y + w01*v01.y + w10*v10.y + w11*v11.y;
                az += w00*v00.z + w01*v01.z + w10*v10.z + w11*v11.z;
                aw += w00*v00.w + w01*v01.w + w10*v10.w + w11*v11.w;
            }
        }
        float inv = 1.0f / fmaxf((float)cnt, 1.0f);
        int idx = n*KIN + cg*49 + bin;   // layout matches reshape: c*49 + bin
        float v0 = ax*inv, v1 = ay*inv, v2 = az*inv, v3 = aw*inv;
        __nv_bfloat16 h;
        h = __float2bfloat16(v0); g_pa_hi[idx]     = h; g_pa_lo[idx]     = __float2bfloat16(v0 - __bfloat162float(h));
        h = __float2bfloat16(v1); g_pa_hi[idx+49]  = h; g_pa_lo[idx+49]  = __float2bfloat16(v1 - __bfloat162float(h));
        h = __float2bfloat16(v2); g_pa_hi[idx+98]  = h; g_pa_lo[idx+98]  = __float2bfloat16(v2 - __bfloat162float(h));
        h = __float2bfloat16(v3); g_pa_hi[idx+147] = h; g_pa_lo[idx+147] = __float2bfloat16(v3 - __bfloat162float(h));
    }
}

// ---------------- bf16 hi/lo split-K GEMM via mma.sync (HMMA) ----------------
// C[m][j] = sum_k A[m][k]*W[j][k]. CTA tile 128x128, BK=32, 8 warps (4x2, 32x64 each).
// 3 passes fused per k16 (AhWh + AhWl + AlWh), fp32 accum. Writes g_part[z].
#define BM 128
#define BN 128
#define BK 32
#define ROWB 80                 // padded row bytes (32 bf16 = 64B + 16B pad)
#define STG_A_HI 0
#define STG_A_LO (BM*ROWB)              // 10240
#define STG_W_HI (2*BM*ROWB)            // 20480
#define STG_W_LO (2*BM*ROWB + BN*ROWB)  // 30720
#define STG_SZ   (2*BM*ROWB + 2*BN*ROWB) // 40960
#define GSMEM    (2*STG_SZ)              // 81920

__global__ void __launch_bounds__(256)
gemm_mma(int asel, const __nv_bfloat16* __restrict__ Whi, const __nv_bfloat16* __restrict__ Wlo,
         int K, int J, int cpz){
    extern __shared__ char smem[];
    uint32_t sb = smem_u32(smem);
    const __nv_bfloat16 *Ahi, *Alo;
    if      (asel == 0){ Ahi = g_pa_hi; Alo = g_pa_lo; }
    else if (asel == 1){ Ahi = g_h1hi;  Alo = g_h1lo;  }
    else               { Ahi = g_f1hi;  Alo = g_f1lo;  }

    int jt  = blockIdx.x*BN;
    int mt  = blockIdx.y*BM;
    int z   = blockIdx.z;
    int tid = threadIdx.x, wid = tid >> 5, lane = tid & 31;
    int wm = wid >> 1, wn = wid & 1;   // warp grid 4 x 2 (32 rows x 64 cols)

    // loader mappings: 128 rows x 4 16B-segs, 2 adjacent segs per thread
    int lrow0 = tid >> 1, lseg0 = (tid & 1) << 1;
    const char* gAh = (const char*)(Ahi) + ((size_t)(mt + lrow0)*K + (size_t)lseg0*8)*2;
    const char* gAl = (const char*)(Alo) + ((size_t)(mt + lrow0)*K + (size_t)lseg0*8)*2;
    const char* gWh = (const char*)(Whi) + ((size_t)(jt + lrow0)*K + (size_t)lseg0*8)*2;
    const char* gWl = (const char*)(Wlo) + ((size_t)(jt + lrow0)*K + (size_t)lseg0*8)*2;
    uint32_t dst = sb + lrow0*ROWB + lseg0*16;
    size_t kstep = (size_t)z*cpz*BK*2;                   // byte offset for this z
    gAh += kstep; gAl += kstep; gWh += kstep; gWl += kstep;

    // ldmatrix per-lane addressing (within a stage)
    uint32_t lrow = lane & 15;
    uint32_t lcol = (lane >> 4) << 4;   // 0 or 16 bytes (k-halves)
    uint32_t aA0 = (wm*32 + 0  + lrow)*ROWB + lcol;
    uint32_t aA1 = (wm*32 + 16 + lrow)*ROWB + lcol;
    uint32_t aW[4];
    #pragma unroll
    for (int p = 0; p < 4; p++) aW[p] = (wn*64 + p*16 + lrow)*ROWB + lcol;

    float acc[2][8][4];
    #pragma unroll
    for (int t = 0; t < 2; t++)
        #pragma unroll
        for (int u = 0; u < 8; u++)
            #pragma unroll
            for (int q = 0; q < 4; q++) acc[t][u][q] = 0.f;

    // prologue: load chunk 0 into stage 0
    {
        CP_ASYNC16(dst + STG_A_HI,      gAh);
        CP_ASYNC16(dst + STG_A_HI + 16, gAh + 16);
        CP_ASYNC16(dst + STG_A_LO,      gAl);
        CP_ASYNC16(dst + STG_A_LO + 16, gAl + 16);
        CP_ASYNC16(dst + STG_W_HI,      gWh);
        CP_ASYNC16(dst + STG_W_HI + 16, gWh + 16);
        CP_ASYNC16(dst + STG_W_LO,      gWl);
        CP_ASYNC16(dst + STG_W_LO + 16, gWl + 16);
        CP_COMMIT();
    }

    for (int c = 0; c < cpz; c++){
        int cs = (c & 1) * STG_SZ;
        // prefetch next chunk into other stage
        if (c + 1 < cpz){
            size_t off = (size_t)(c + 1)*BK*2;
            int ns = ((c + 1) & 1) * STG_SZ;
            CP_ASYNC16(dst + ns + STG_A_HI,      gAh + off);
            CP_ASYNC16(dst + ns + STG_A_HI + 16, gAh + off + 16);
            CP_ASYNC16(dst + ns + STG_A_LO,      gAl + off);
            CP_ASYNC16(dst + ns + STG_A_LO + 16, gAl + off + 16);
            CP_ASYNC16(dst + ns + STG_W_HI,      gWh + off);
            CP_ASYNC16(dst + ns + STG_W_HI + 16, gWh + off + 16);
            CP_ASYNC16(dst + ns + STG_W_LO,      gWl + off);
            CP_ASYNC16(dst + ns + STG_W_LO + 16, gWl + off + 16);
            CP_COMMIT();
            CP_WAIT1();
        } else {
            CP_WAIT0();
        }
        __syncthreads();

        #pragma unroll
        for (int ks = 0; ks < 2; ks++){
            uint32_t kb = cs + ks*32;
            uint32_t ah[2][4], al[2][4], wh[4][4], wl[4][4];
            ldm_x4(ah[0][0], ah[0][1], ah[0][2], ah[0][3], sb + STG_A_HI + kb + aA0);
            ldm_x4(ah[1][0], ah[1][1], ah[1][2], ah[1][3], sb + STG_A_HI + kb + aA1);
            ldm_x4(al[0][0], al[0][1], al[0][2], al[0][3], sb + STG_A_LO + kb + aA0);
            ldm_x4(al[1][0], al[1][1], al[1][2], al[1][3], sb + STG_A_LO + kb + aA1);
            #pragma unroll
            for (int p = 0; p < 4; p++){
                ldm_x4(wh[p][0], wh[p][1], wh[p][2], wh[p][3], sb + STG_W_HI + kb + aW[p]);
                ldm_x4(wl[p][0], wl[p][1], wl[p][2], wl[p][3], sb + STG_W_LO + kb + aW[p]);
            }
            // n8-tile u (0..7): pair p = u>>1, regs {r[u&1], r[(u&1)+2]}
            #pragma unroll
            for (int t = 0; t < 2; t++){
                #pragma unroll
                for (int u = 0; u < 8; u++){
                    int p = u >> 1, s = u & 1;
                    uint32_t bh0 = wh[p][s], bh1 = wh[p][s+2];
                    uint32_t bl0 = wl[p][s], bl1 = wl[p][s+2];
                    mma16816(acc[t][u], ah[t][0], ah[t][1], ah[t][2], ah[t][3], bh0, bh1);
                    mma16816(acc[t][u], ah[t][0], ah[t][1], ah[t][2], ah[t][3], bl0, bl1);
                    mma16816(acc[t][u], al[t][0], al[t][1], al[t][2], al[t][3], bh0, bh1);
                }
            }
        }
        __syncthreads();
    }

    // epilogue: write split-K partials
    int gmb = mt + wm*32;
    int gjb = jt + wn*64;
    int r0 = lane >> 2, c0 = (lane & 3) << 1;
    #pragma unroll
    for (int t = 0; t < 2; t++){
        #pragma unroll
        for (int u = 0; u < 8; u++){
            int gm = gmb + t*16 + r0;
            int gj = gjb + u*8 + c0;
            float2 lo = make_float2(acc[t][u][0], acc[t][u][1]);
            float2 hi = make_float2(acc[t][u][2], acc[t][u][3]);
            *(float2*)(g_part + ((size_t)z*N_ROIS + gm    )*J + gj) = lo;
            *(float2*)(g_part + ((size_t)z*N_ROIS + gm + 8)*J + gj) = hi;
        }
    }
}

// ---------------- split-K reduction + bias + relu (+ hi/lo conversion), float4 ----------------
__global__ void reduce_bias_relu(int osel, const float* __restrict__ bias, int MJ, int J, int SK){
    int i4 = blockIdx.x*256 + threadIdx.x;       // float4 index
    if (i4 >= MJ/4) return;
    int MJ4 = MJ >> 2;
    float4 s = ((const float4*)g_part)[i4];
    for (int zz = 1; zz < SK; zz++){
        float4 p = ((const float4*)g_part)[(size_t)zz*MJ4 + i4];
        s.x += p.x; s.y += p.y; s.z += p.z; s.w += p.w;
    }
    float4 bv = ((const float4*)bias)[i4 % (J >> 2)];
    s.x = fmaxf(s.x + bv.x, 0.f);
    s.y = fmaxf(s.y + bv.y, 0.f);
    s.z = fmaxf(s.z + bv.z, 0.f);
    s.w = fmaxf(s.w + bv.w, 0.f);
    if (osel == 1){ ((float4*)g_h2)[i4] = s; return; }
    if (osel == 3){ ((float4*)g_f2)[i4] = s; return; }
    __nv_bfloat16 h0 = __float2bfloat16(s.x), h1 = __float2bfloat16(s.y);
    __nv_bfloat16 h2 = __float2bfloat16(s.z), h3 = __float2bfloat16(s.w);
    __nv_bfloat16 l0 = __float2bfloat16(s.x - __bfloat162float(h0));
    __nv_bfloat16 l1 = __float2bfloat16(s.y - __bfloat162float(h1));
    __nv_bfloat16 l2 = __float2bfloat16(s.z - __bfloat162float(h2));
    __nv_bfloat16 l3 = __float2bfloat16(s.w - __bfloat162float(h3));
    ushort4 hv = make_ushort4(*(unsigned short*)&h0, *(unsigned short*)&h1,
                              *(unsigned short*)&h2, *(unsigned short*)&h3);
    ushort4 lv = make_ushort4(*(unsigned short*)&l0, *(unsigned short*)&l1,
                              *(unsigned short*)&l2, *(unsigned short*)&l3);
    if (osel == 0){ ((ushort4*)g_h1hi)[i4] = hv; ((ushort4*)g_h1lo)[i4] = lv; }
    else          { ((ushort4*)g_f1hi)[i4] = hv; ((ushort4*)g_f1lo)[i4] = lv; }
}

// ---------------- small-J heads (fp32 warp dots, float4) ----------------
__global__ void smalldot(int asel, const float* __restrict__ Wt, const float* __restrict__ bias,
                         float* outp, int K, int J){
    const float* A = (asel == 0) ? g_h2 : g_f2;
    float* O = outp ? outp : g_off;
    int m    = blockIdx.x;
    int warp = threadIdx.x >> 5;
    int lane = threadIdx.x & 31;
    const float4* a = (const float4*)(A + (size_t)m*K);
    int K4 = K >> 2;
    for (int j = warp; j < J; j += 8){
        const float4* w = (const float4*)(Wt + (size_t)j*K);
        float s = 0.f;
        for (int k = lane; k < K4; k += 32){
            float4 av = a[k], wv = w[k];
            s += av.x*wv.x + av.y*wv.y + av.z*wv.z + av.w*wv.w;
        }
        #pragma unroll
        for (int o = 16; o; o >>= 1) s += __shfl_xor_sync(0xffffffffu, s, o);
        if (lane == 0) O[m*J + j] = s + bias[j];
    }
}

// ---------------- launch ----------------
extern "C" void kernel_launch(void* const* d_in, const int* in_sizes, int n_in,
                              void* d_out, int out_size){
    const float* x    = (const float*)d_in[0];
    const float* rois = (const float*)d_in[1];
    const float* ow1  = (const float*)d_in[2];
    const float* ob1  = (const float*)d_in[3];
    const float* ow2  = (const float*)d_in[4];
    const float* ob2  = (const float*)d_in[5];
    const float* ow3  = (const float*)d_in[6];
    const float* ob3  = (const float*)d_in[7];
    const float* f1w  = (const float*)d_in[8];
    const float* f1b  = (const float*)d_in[9];
    const float* f2w  = (const float*)d_in[10];
    const float* f2b  = (const float*)d_in[11];
    const float* bxw  = (const float*)d_in[12];
    const float* bxb  = (const float*)d_in[13];

    cudaFuncSetAttribute(gemm_mma, cudaFuncAttributeMaxDynamicSharedMemorySize, GSMEM);

    __nv_bfloat16 *w1hi, *w1lo, *w2hi, *w2lo, *fw1hi, *fw1lo, *fw2hi, *fw2lo;
    cudaGetSymbolAddress((void**)&w1hi,  g_w1hi);  cudaGetSymbolAddress((void**)&w1lo,  g_w1lo);
    cudaGetSymbolAddress((void**)&w2hi,  g_w2hi);  cudaGetSymbolAddress((void**)&w2lo,  g_w2lo);
    cudaGetSymbolAddress((void**)&fw1hi, g_fw1hi); cudaGetSymbolAddress((void**)&fw1lo, g_fw1lo);
    cudaGetSymbolAddress((void**)&fw2hi, g_fw2hi); cudaGetSymbolAddress((void**)&fw2lo, g_fw2lo);

    nchw2nhwc<<<BIMG*HH*WW, CCH>>>(x);

    convw<<<(DFC*KIN/4 + 255)/256, 256>>>(ow1, w1hi, w1lo, DFC*KIN/4);
    convw<<<(DFC*DFC/4 + 255)/256, 256>>>(ow2, w2hi, w2lo, DFC*DFC/4);
    convw<<<(FCC*KIN/4 + 255)/256, 256>>>(f1w, fw1hi, fw1lo, FCC*KIN/4);
    convw<<<(FCC*FCC/4 + 255)/256, 256>>>(f2w, fw2hi, fw2lo, FCC*FCC/4);

    pool_kernel<<<dim3(N_ROIS,2), 256>>>(rois, 0);

    // h1 = relu(p @ ow1^T + b1)  [256x1024], K=12544 (392 chunks): SK=14, cpz=28
    gemm_mma<<<dim3(8,2,14), 256, GSMEM>>>(0, w1hi, w1lo, KIN, DFC, 28);
    reduce_bias_relu<<<(N_ROIS*DFC/4)/256, 256>>>(0, ob1, N_ROIS*DFC, DFC, 14);

    // h2 = relu(h1 @ ow2^T + b2)  K=1024 (32 chunks): SK=16, cpz=2
    gemm_mma<<<dim3(8,2,16), 256, GSMEM>>>(1, w2hi, w2lo, DFC, DFC, 2);
    reduce_bias_relu<<<(N_ROIS*DFC/4)/256, 256>>>(1, ob2, N_ROIS*DFC, DFC, 16);

    // off = h2 @ ow3^T + b3  [256x98]
    smalldot<<<N_ROIS, 256>>>(0, ow3, ob3, nullptr, DFC, 98);

    pool_kernel<<<dim3(N_ROIS,2), 256>>>(rois, 1);

    // f1 = relu(p @ f1w^T + b)  [256x512], K=12544 (392 chunks): SK=28, cpz=14
    gemm_mma<<<dim3(4,2,28), 256, GSMEM>>>(0, fw1hi, fw1lo, KIN, FCC, 14);
    reduce_bias_relu<<<(N_ROIS*FCC/4)/256, 256>>>(2, f1b, N_ROIS*FCC, FCC, 28);

    // f2 = relu(f1 @ f2w^T + b)  K=512 (16 chunks): SK=16, cpz=1
    gemm_mma<<<dim3(4,2,16), 256, GSMEM>>>(2, fw2hi, fw2lo, FCC, FCC, 1);
    reduce_bias_relu<<<(N_ROIS*FCC/4)/256, 256>>>(3, f2b, N_ROIS*FCC, FCC, 16);

    // out = f2 @ box_w^T + box_b  [256x4]
    smalldot<<<N_ROIS, 256>>>(1, bxw, bxb, (float*)d_out, FCC, 4);
}

// round 12
// speedup vs baseline: 1.5051x; 1.1396x over previous
#include <cuda_runtime.h>
#include <cuda_bf16.h>
#include <cuda_fp16.h>
#include <cstdint>

// Problem constants
#define N_ROIS 256
#define CCH    256
#define HH     25
#define WW     25
#define BIMG   8
#define KIN    12544   // 256*49
#define DFC    1024
#define FCC    512
#define SSC    (25.0f/255.0f)

// ---------------- scratch (static device globals; no allocs) ----------------
__device__ __align__(256) float g_xt[BIMG*HH*WW*CCH];        // NHWC feature map
__device__ __align__(256) __half g_pa_hi[N_ROIS*KIN];        // pooled fp16 hi
__device__ __align__(256) __half g_pa_lo[N_ROIS*KIN];        // pooled fp16 lo
__device__ __align__(256) __nv_bfloat16 g_h1hi[N_ROIS*DFC];
__device__ __align__(256) __nv_bfloat16 g_h1lo[N_ROIS*DFC];
__device__ __align__(256) float g_h2[N_ROIS*DFC];
__device__ __align__(256) __nv_bfloat16 g_f1hi[N_ROIS*FCC];
__device__ __align__(256) __nv_bfloat16 g_f1lo[N_ROIS*FCC];
__device__ __align__(256) float g_f2[N_ROIS*FCC];
__device__ __align__(256) float g_off[N_ROIS*98];
__device__ __align__(256) float g_part[5*1024*1024];
// converted weights
__device__ __align__(256) __half g_w1f [DFC*KIN];            // fp16 single
__device__ __align__(256) __half g_fw1f[FCC*KIN];            // fp16 single
__device__ __align__(256) __nv_bfloat16 g_w2hi [DFC*DFC];
__device__ __align__(256) __nv_bfloat16 g_w2lo [DFC*DFC];
__device__ __align__(256) __nv_bfloat16 g_fw2hi[FCC*FCC];
__device__ __align__(256) __nv_bfloat16 g_fw2lo[FCC*FCC];

// ---------------- helpers ----------------
__device__ __forceinline__ uint32_t smem_u32(const void* p){
    uint32_t a;
    asm("{ .reg .u64 t; cvta.to.shared.u64 t, %1; cvt.u32.u64 %0, t; }" : "=r"(a) : "l"(p));
    return a;
}
#define CP_ASYNC16(dst, src) \
    asm volatile("cp.async.cg.shared.global [%0], [%1], 16;" :: "r"(dst), "l"(src) : "memory")
#define CP_COMMIT() asm volatile("cp.async.commit_group;" ::: "memory")
#define CP_WAIT2()  asm volatile("cp.async.wait_group 2;" ::: "memory")
#define CP_WAIT1()  asm volatile("cp.async.wait_group 1;" ::: "memory")
#define CP_WAIT0()  asm volatile("cp.async.wait_group 0;" ::: "memory")

__device__ __forceinline__ void ldm_x4(uint32_t& r0, uint32_t& r1, uint32_t& r2, uint32_t& r3,
                                       uint32_t addr){
    asm volatile("ldmatrix.sync.aligned.m8n8.x4.shared.b16 {%0,%1,%2,%3}, [%4];"
                 : "=r"(r0), "=r"(r1), "=r"(r2), "=r"(r3) : "r"(addr));
}
__device__ __forceinline__ void mma_bf16(float* c, uint32_t a0, uint32_t a1, uint32_t a2,
                                         uint32_t a3, uint32_t b0, uint32_t b1){
    asm volatile("mma.sync.aligned.m16n8k16.row.col.f32.bf16.bf16.f32 "
                 "{%0,%1,%2,%3}, {%4,%5,%6,%7}, {%8,%9}, {%0,%1,%2,%3};"
                 : "+f"(c[0]), "+f"(c[1]), "+f"(c[2]), "+f"(c[3])
                 : "r"(a0), "r"(a1), "r"(a2), "r"(a3), "r"(b0), "r"(b1));
}
__device__ __forceinline__ void mma_f16(float* c, uint32_t a0, uint32_t a1, uint32_t a2,
                                        uint32_t a3, uint32_t b0, uint32_t b1){
    asm volatile("mma.sync.aligned.m16n8k16.row.col.f32.f16.f16.f32 "
                 "{%0,%1,%2,%3}, {%4,%5,%6,%7}, {%8,%9}, {%0,%1,%2,%3};"
                 : "+f"(c[0]), "+f"(c[1]), "+f"(c[2]), "+f"(c[3])
                 : "r"(a0), "r"(a1), "r"(a2), "r"(a3), "r"(b0), "r"(b1));
}

// ---------------- NCHW -> NHWC transpose ----------------
__global__ void nchw2nhwc(const float* __restrict__ x){
    int pidx = blockIdx.x;
    int c    = threadIdx.x;
    int b  = pidx / (HH*WW);
    int hw = pidx - b*(HH*WW);
    g_xt[(b*(HH*WW) + hw)*CCH + c] = x[(b*CCH + c)*(HH*WW) + hw];
}

// ---------------- fp32 -> fp16 single weight conversion ----------------
__global__ void convw_f16(const float* __restrict__ s, __half* __restrict__ o, int n4){
    int i = blockIdx.x*256 + threadIdx.x;
    if (i >= n4) return;
    float4 v = ((const float4*)s)[i];
    __half h0 = __float2half(v.x), h1 = __float2half(v.y);
    __half h2 = __float2half(v.z), h3 = __float2half(v.w);
    ushort4 hv = make_ushort4(*(unsigned short*)&h0, *(unsigned short*)&h1,
                              *(unsigned short*)&h2, *(unsigned short*)&h3);
    ((ushort4*)o)[i] = hv;
}

// ---------------- fp32 -> hi/lo bf16 weight conversion ----------------
__global__ void convw(const float* __restrict__ s, __nv_bfloat16* __restrict__ hi,
                      __nv_bfloat16* __restrict__ lo, int n4){
    int i = blockIdx.x*256 + threadIdx.x;
    if (i >= n4) return;
    float4 v = ((const float4*)s)[i];
    __nv_bfloat16 h0 = __float2bfloat16(v.x), h1 = __float2bfloat16(v.y);
    __nv_bfloat16 h2 = __float2bfloat16(v.z), h3 = __float2bfloat16(v.w);
    __nv_bfloat16 l0 = __float2bfloat16(v.x - __bfloat162float(h0));
    __nv_bfloat16 l1 = __float2bfloat16(v.y - __bfloat162float(h1));
    __nv_bfloat16 l2 = __float2bfloat16(v.z - __bfloat162float(h2));
    __nv_bfloat16 l3 = __float2bfloat16(v.w - __bfloat162float(h3));
    ushort4 hv = make_ushort4(*(unsigned short*)&h0, *(unsigned short*)&h1,
                              *(unsigned short*)&h2, *(unsigned short*)&h3);
    ushort4 lv = make_ushort4(*(unsigned short*)&l0, *(unsigned short*)&l1,
                              *(unsigned short*)&l2, *(unsigned short*)&l3);
    ((ushort4*)hi)[i] = hv;
    ((ushort4*)lo)[i] = lv;
}

// ---------------- deformable ROI pool (writes fp16 hi/lo pooled features) ----------------
__global__ void __launch_bounds__(256) pool_kernel(const float* __restrict__ rois, int use_off){
    int n    = blockIdx.x;
    int half = blockIdx.y;
    int tid  = threadIdx.x;
    int cg   = ((tid & 31) << 2) + half*128;
    int bs   = tid >> 5;

    const float* r = rois + n*5;
    int   b  = (int)r[0];
    float sw = rintf(r[1])*SSC - 0.5f;
    float sh = rintf(r[2])*SSC - 0.5f;
    float rw = fmaxf((rintf(r[3]) + 1.0f)*SSC - 0.5f - sw, 0.1f);
    float rh = fmaxf((rintf(r[4]) + 1.0f)*SSC - 0.5f - sh, 0.1f);
    float bw = rw / 7.0f, bh = rh / 7.0f;
    float bwq = bw*0.25f, bhq = bh*0.25f;

    for(int bin = bs; bin < 49; bin += 8){
        int ph = bin / 7, pw = bin - ph*7;
        float tx = use_off ? g_off[n*98 + bin]      * 0.1f : 0.0f;
        float ty = use_off ? g_off[n*98 + 49 + bin] * 0.1f : 0.0f;
        float wst = pw*bw + sw + tx*rw;
        float hst = ph*bh + sh + ty*rh;

        float ax=0.f, ay=0.f, az=0.f, aw=0.f;
        int cnt = 0;
        #pragma unroll
        for(int iy=0; iy<4; iy++){
            float sy = hst + iy*bhq;
            bool  vy = (sy >= -0.5f) && (sy <= (float)HH - 0.5f);
            float yc  = fminf(fmaxf(sy, 0.0f), (float)(HH-1));
            float y0f = floorf(yc);
            float dy  = yc - y0f;
            int yi0 = (int)y0f;
            int yi1 = (int)ceilf(yc);
            #pragma unroll
            for(int ix=0; ix<4; ix++){
                float sx = wst + ix*bwq;
                if(!vy || sx < -0.5f || sx > (float)WW - 0.5f) continue;
                cnt++;
                float xc  = fminf(fmaxf(sx, 0.0f), (float)(WW-1));
                float x0f = floorf(xc);
                float dx  = xc - x0f;
                int xi0 = (int)x0f;
                int xi1 = (int)ceilf(xc);
                int rb0 = (b*HH + yi0)*WW;
                int rb1 = (b*HH + yi1)*WW;
                float4 v00 = *(const float4*)(g_xt + (rb0 + xi0)*CCH + cg);
                float4 v01 = *(const float4*)(g_xt + (rb0 + xi1)*CCH + cg);
                float4 v10 = *(const float4*)(g_xt + (rb1 + xi0)*CCH + cg);
                float4 v11 = *(const float4*)(g_xt + (rb1 + xi1)*CCH + cg);
                float w00 = (1.f-dx)*(1.f-dy), w01 = dx*(1.f-dy);
                float w10 = (1.f-dx)*dy,       w11 = dx*dy;
                ax += w00*v00.x + w01*v01.x + w10*v10.x + w11*v11.x;
                ay += w00*v00.y + w01*v01.y + w10*v10.y + w11*v11.y;
                az += w00*v00.z + w01*v01.z + w10*v10.z + w11*v11.z;
                aw += w00*v00.w + w01*v01.w + w10*v10.w + w11*v11.w;
            }
        }
        float inv = 1.0f / fmaxf((float)cnt, 1.0f);
        int idx = n*KIN + cg*49 + bin;   // layout matches reshape: c*49 + bin
        float v0 = ax*inv, v1 = ay*inv, v2 = az*inv, v3 = aw*inv;
        __half h;
        h = __float2half(v0); g_pa_hi[idx]     = h; g_pa_lo[idx]     = __float2half(v0 - __half2float(h));
        h = __float2half(v1); g_pa_hi[idx+49]  = h; g_pa_lo[idx+49]  = __float2half(v1 - __half2float(h));
        h = __float2half(v2); g_pa_hi[idx+98]  = h; g_pa_lo[idx+98]  = __float2half(v2 - __half2float(h));
        h = __float2half(v3); g_pa_hi[idx+147] = h; g_pa_lo[idx+147] = __float2half(v3 - __half2float(h));
    }
}

// ================= tile geometry (shared by both gemm kernels) =================
#define BM 128
#define BN 128
#define BK 32
#define ROWB 80                 // padded row bytes (32 x 2B = 64B + 16B pad)

// ---------------- 2-pass fp16 split-K GEMM (big GEMMs: A = pooled feats) ----------------
// C = A @ W^T, A = ah+al (fp16 split), W = wh (fp16). 3-stage cp.async pipeline.
#define F_A_HI 0
#define F_A_LO (BM*ROWB)                // 10240
#define F_W    (2*BM*ROWB)              // 20480
#define F_STG  (2*BM*ROWB + BN*ROWB)    // 30720
#define GSMEM_F16 (3*F_STG)             // 92160

__global__ void __launch_bounds__(256)
gemm_f16(const __half* __restrict__ Wf, int K, int J, int cpz){
    extern __shared__ char smem[];
    uint32_t sb = smem_u32(smem);
    int jt  = blockIdx.x*BN;
    int mt  = blockIdx.y*BM;
    int z   = blockIdx.z;
    int tid = threadIdx.x, wid = tid >> 5, lane = tid & 31;
    int wm = wid >> 1, wn = wid & 1;   // 4 x 2 warps (32 rows x 64 cols)

    // loaders: 128 rows x 4 segs of 16B, 2 adjacent segs per thread
    int lrow0 = tid >> 1, lseg0 = (tid & 1) << 1;
    size_t kstep = (size_t)z*cpz*BK*2;
    const char* gAh = (const char*)(g_pa_hi) + ((size_t)(mt + lrow0)*K + (size_t)lseg0*8)*2 + kstep;
    const char* gAl = (const char*)(g_pa_lo) + ((size_t)(mt + lrow0)*K + (size_t)lseg0*8)*2 + kstep;
    const char* gW  = (const char*)(Wf)      + ((size_t)(jt + lrow0)*K + (size_t)lseg0*8)*2 + kstep;
    uint32_t dst = sb + lrow0*ROWB + lseg0*16;

    uint32_t lrow = lane & 15;
    uint32_t lcol = (lane >> 4) << 4;
    uint32_t aA0 = (wm*32 + 0  + lrow)*ROWB + lcol;
    uint32_t aA1 = (wm*32 + 16 + lrow)*ROWB + lcol;
    uint32_t aW[4];
    #pragma unroll
    for (int p = 0; p < 4; p++) aW[p] = (wn*64 + p*16 + lrow)*ROWB + lcol;

    float acc[2][8][4];
    #pragma unroll
    for (int t = 0; t < 2; t++)
        #pragma unroll
        for (int u = 0; u < 8; u++)
            #pragma unroll
            for (int q = 0; q < 4; q++) acc[t][u][q] = 0.f;

    // prologue: issue chunks 0 and 1
    {
        CP_ASYNC16(dst + F_A_HI,      gAh);
        CP_ASYNC16(dst + F_A_HI + 16, gAh + 16);
        CP_ASYNC16(dst + F_A_LO,      gAl);
        CP_ASYNC16(dst + F_A_LO + 16, gAl + 16);
        CP_ASYNC16(dst + F_W,         gW);
        CP_ASYNC16(dst + F_W + 16,    gW + 16);
        CP_COMMIT();
    }
    if (cpz > 1){
        size_t off = (size_t)BK*2;
        uint32_t ns = dst + F_STG;
        CP_ASYNC16(ns + F_A_HI,      gAh + off);
        CP_ASYNC16(ns + F_A_HI + 16, gAh + off + 16);
        CP_ASYNC16(ns + F_A_LO,      gAl + off);
        CP_ASYNC16(ns + F_A_LO + 16, gAl + off + 16);
        CP_ASYNC16(ns + F_W,         gW  + off);
        CP_ASYNC16(ns + F_W + 16,    gW  + off + 16);
        CP_COMMIT();
    }

    for (int c = 0; c < cpz; c++){
        if (c + 2 < cpz){
            size_t off = (size_t)(c + 2)*BK*2;
            uint32_t ns = dst + ((c + 2) % 3)*F_STG;
            CP_ASYNC16(ns + F_A_HI,      gAh + off);
            CP_ASYNC16(ns + F_A_HI + 16, gAh + off + 16);
            CP_ASYNC16(ns + F_A_LO,      gAl + off);
            CP_ASYNC16(ns + F_A_LO + 16, gAl + off + 16);
            CP_ASYNC16(ns + F_W,         gW  + off);
            CP_ASYNC16(ns + F_W + 16,    gW  + off + 16);
            CP_COMMIT();
            CP_WAIT2();
        } else if (c + 1 < cpz){
            CP_WAIT1();
        } else {
            CP_WAIT0();
        }
        __syncthreads();

        uint32_t cs = (c % 3)*F_STG;
        #pragma unroll
        for (int ks = 0; ks < 2; ks++){
            uint32_t kb = cs + ks*32;
            uint32_t ah[2][4], al[2][4], wh[4][4];
            ldm_x4(ah[0][0], ah[0][1], ah[0][2], ah[0][3], sb + F_A_HI + kb + aA0);
            ldm_x4(ah[1][0], ah[1][1], ah[1][2], ah[1][3], sb + F_A_HI + kb + aA1);
            ldm_x4(al[0][0], al[0][1], al[0][2], al[0][3], sb + F_A_LO + kb + aA0);
            ldm_x4(al[1][0], al[1][1], al[1][2], al[1][3], sb + F_A_LO + kb + aA1);
            #pragma unroll
            for (int p = 0; p < 4; p++)
                ldm_x4(wh[p][0], wh[p][1], wh[p][2], wh[p][3], sb + F_W + kb + aW[p]);
            #pragma unroll
            for (int t = 0; t < 2; t++){
                #pragma unroll
                for (int u = 0; u < 8; u++){
                    int p = u >> 1, s = u & 1;
                    uint32_t b0 = wh[p][s], b1 = wh[p][s+2];
                    mma_f16(acc[t][u], ah[t][0], ah[t][1], ah[t][2], ah[t][3], b0, b1);
                    mma_f16(acc[t][u], al[t][0], al[t][1], al[t][2], al[t][3], b0, b1);
                }
            }
        }
        __syncthreads();
    }

    int gmb = mt + wm*32;
    int gjb = jt + wn*64;
    int r0 = lane >> 2, c0 = (lane & 3) << 1;
    #pragma unroll
    for (int t = 0; t < 2; t++){
        #pragma unroll
        for (int u = 0; u < 8; u++){
            int gm = gmb + t*16 + r0;
            int gj = gjb + u*8 + c0;
            float2 lo = make_float2(acc[t][u][0], acc[t][u][1]);
            float2 hi = make_float2(acc[t][u][2], acc[t][u][3]);
            *(float2*)(g_part + ((size_t)z*N_ROIS + gm    )*J + gj) = lo;
            *(float2*)(g_part + ((size_t)z*N_ROIS + gm + 8)*J + gj) = hi;
        }
    }
}

// ---------------- 3-pass bf16 hi/lo split-K GEMM (small GEMMs h2, f2) ----------------
#define STG_A_HI 0
#define STG_A_LO (BM*ROWB)              // 10240
#define STG_W_HI (2*BM*ROWB)            // 20480
#define STG_W_LO (2*BM*ROWB + BN*ROWB)  // 30720
#define STG_SZ   (2*BM*ROWB + 2*BN*ROWB) // 40960
#define GSMEM    (2*STG_SZ)              // 81920

__global__ void __launch_bounds__(256)
gemm_mma(int asel, const __nv_bfloat16* __restrict__ Whi, const __nv_bfloat16* __restrict__ Wlo,
         int K, int J, int cpz){
    extern __shared__ char smem[];
    uint32_t sb = smem_u32(smem);
    const __nv_bfloat16 *Ahi, *Alo;
    if (asel == 1){ Ahi = g_h1hi; Alo = g_h1lo; }
    else          { Ahi = g_f1hi; Alo = g_f1lo; }

    int jt  = blockIdx.x*BN;
    int mt  = blockIdx.y*BM;
    int z   = blockIdx.z;
    int tid = threadIdx.x, wid = tid >> 5, lane = tid & 31;
    int wm = wid >> 1, wn = wid & 1;

    int lrow0 = tid >> 1, lseg0 = (tid & 1) << 1;
    const char* gAh = (const char*)(Ahi) + ((size_t)(mt + lrow0)*K + (size_t)lseg0*8)*2;
    const char* gAl = (const char*)(Alo) + ((size_t)(mt + lrow0)*K + (size_t)lseg0*8)*2;
    const char* gWh = (const char*)(Whi) + ((size_t)(jt + lrow0)*K + (size_t)lseg0*8)*2;
    const char* gWl = (const char*)(Wlo) + ((size_t)(jt + lrow0)*K + (size_t)lseg0*8)*2;
    uint32_t dst = sb + lrow0*ROWB + lseg0*16;
    size_t kstep = (size_t)z*cpz*BK*2;
    gAh += kstep; gAl += kstep; gWh += kstep; gWl += kstep;

    uint32_t lrow = lane & 15;
    uint32_t lcol = (lane >> 4) << 4;
    uint32_t aA0 = (wm*32 + 0  + lrow)*ROWB + lcol;
    uint32_t aA1 = (wm*32 + 16 + lrow)*ROWB + lcol;
    uint32_t aW[4];
    #pragma unroll
    for (int p = 0; p < 4; p++) aW[p] = (wn*64 + p*16 + lrow)*ROWB + lcol;

    float acc[2][8][4];
    #pragma unroll
    for (int t = 0; t < 2; t++)
        #pragma unroll
        for (int u = 0; u < 8; u++)
            #pragma unroll
            for (int q = 0; q < 4; q++) acc[t][u][q] = 0.f;

    {
        CP_ASYNC16(dst + STG_A_HI,      gAh);
        CP_ASYNC16(dst + STG_A_HI + 16, gAh + 16);
        CP_ASYNC16(dst + STG_A_LO,      gAl);
        CP_ASYNC16(dst + STG_A_LO + 16, gAl + 16);
        CP_ASYNC16(dst + STG_W_HI,      gWh);
        CP_ASYNC16(dst + STG_W_HI + 16, gWh + 16);
        CP_ASYNC16(dst + STG_W_LO,      gWl);
        CP_ASYNC16(dst + STG_W_LO + 16, gWl + 16);
        CP_COMMIT();
    }

    for (int c = 0; c < cpz; c++){
        int cs = (c & 1) * STG_SZ;
        if (c + 1 < cpz){
            size_t off = (size_t)(c + 1)*BK*2;
            int ns = ((c + 1) & 1) * STG_SZ;
            CP_ASYNC16(dst + ns + STG_A_HI,      gAh + off);
            CP_ASYNC16(dst + ns + STG_A_HI + 16, gAh + off + 16);
            CP_ASYNC16(dst + ns + STG_A_LO,      gAl + off);
            CP_ASYNC16(dst + ns + STG_A_LO + 16, gAl + off + 16);
            CP_ASYNC16(dst + ns + STG_W_HI,      gWh + off);
            CP_ASYNC16(dst + ns + STG_W_HI + 16, gWh + off + 16);
            CP_ASYNC16(dst + ns + STG_W_LO,      gWl + off);
            CP_ASYNC16(dst + ns + STG_W_LO + 16, gWl + off + 16);
            CP_COMMIT();
            CP_WAIT1();
        } else {
            CP_WAIT0();
        }
        __syncthreads();

        #pragma unroll
        for (int ks = 0; ks < 2; ks++){
            uint32_t kb = cs + ks*32;
            uint32_t ah[2][4], al[2][4], wh[4][4], wl[4][4];
            ldm_x4(ah[0][0], ah[0][1], ah[0][2], ah[0][3], sb + STG_A_HI + kb + aA0);
            ldm_x4(ah[1][0], ah[1][1], ah[1][2], ah[1][3], sb + STG_A_HI + kb + aA1);
            ldm_x4(al[0][0], al[0][1], al[0][2], al[0][3], sb + STG_A_LO + kb + aA0);
            ldm_x4(al[1][0], al[1][1], al[1][2], al[1][3], sb + STG_A_LO + kb + aA1);
            #pragma unroll
            for (int p = 0; p < 4; p++){
                ldm_x4(wh[p][0], wh[p][1], wh[p][2], wh[p][3], sb + STG_W_HI + kb + aW[p]);
                ldm_x4(wl[p][0], wl[p][1], wl[p][2], wl[p][3], sb + STG_W_LO + kb + aW[p]);
            }
            #pragma unroll
            for (int t = 0; t < 2; t++){
                #pragma unroll
                for (int u = 0; u < 8; u++){
                    int p = u >> 1, s = u & 1;
                    uint32_t bh0 = wh[p][s], bh1 = wh[p][s+2];
                    uint32_t bl0 = wl[p][s], bl1 = wl[p][s+2];
                    mma_bf16(acc[t][u], ah[t][0], ah[t][1], ah[t][2], ah[t][3], bh0, bh1);
                    mma_bf16(acc[t][u], ah[t][0], ah[t][1], ah[t][2], ah[t][3], bl0, bl1);
                    mma_bf16(acc[t][u], al[t][0], al[t][1], al[t][2], al[t][3], bh0, bh1);
                }
            }
        }
        __syncthreads();
    }

    int gmb = mt + wm*32;
    int gjb = jt + wn*64;
    int r0 = lane >> 2, c0 = (lane & 3) << 1;
    #pragma unroll
    for (int t = 0; t < 2; t++){
        #pragma unroll
        for (int u = 0; u < 8; u++){
            int gm = gmb + t*16 + r0;
            int gj = gjb + u*8 + c0;
            float2 lo = make_float2(acc[t][u][0], acc[t][u][1]);
            float2 hi = make_float2(acc[t][u][2], acc[t][u][3]);
            *(float2*)(g_part + ((size_t)z*N_ROIS + gm    )*J + gj) = lo;
            *(float2*)(g_part + ((size_t)z*N_ROIS + gm + 8)*J + gj) = hi;
        }
    }
}

// ---------------- split-K reduction + bias + relu (+ hi/lo conversion), float4 ----------------
__global__ void reduce_bias_relu(int osel, const float* __restrict__ bias, int MJ, int J, int SK){
    int i4 = blockIdx.x*256 + threadIdx.x;       // float4 index
    if (i4 >= MJ/4) return;
    int MJ4 = MJ >> 2;
    float4 s = ((const float4*)g_part)[i4];
    for (int zz = 1; zz < SK; zz++){
        float4 p = ((const float4*)g_part)[(size_t)zz*MJ4 + i4];
        s.x += p.x; s.y += p.y; s.z += p.z; s.w += p.w;
    }
    float4 bv = ((const float4*)bias)[i4 % (J >> 2)];
    s.x = fmaxf(s.x + bv.x, 0.f);
    s.y = fmaxf(s.y + bv.y, 0.f);
    s.z = fmaxf(s.z + bv.z, 0.f);
    s.w = fmaxf(s.w + bv.w, 0.f);
    if (osel == 1){ ((float4*)g_h2)[i4] = s; return; }
    if (osel == 3){ ((float4*)g_f2)[i4] = s; return; }
    __nv_bfloat16 h0 = __float2bfloat16(s.x), h1 = __float2bfloat16(s.y);
    __nv_bfloat16 h2 = __float2bfloat16(s.z), h3 = __float2bfloat16(s.w);
    __nv_bfloat16 l0 = __float2bfloat16(s.x - __bfloat162float(h0));
    __nv_bfloat16 l1 = __float2bfloat16(s.y - __bfloat162float(h1));
    __nv_bfloat16 l2 = __float2bfloat16(s.z - __bfloat162float(h2));
    __nv_bfloat16 l3 = __float2bfloat16(s.w - __bfloat162float(h3));
    ushort4 hv = make_ushort4(*(unsigned short*)&h0, *(unsigned short*)&h1,
                              *(unsigned short*)&h2, *(unsigned short*)&h3);
    ushort4 lv = make_ushort4(*(unsigned short*)&l0, *(unsigned short*)&l1,
                              *(unsigned short*)&l2, *(unsigned short*)&l3);
    if (osel == 0){ ((ushort4*)g_h1hi)[i4] = hv; ((ushort4*)g_h1lo)[i4] = lv; }
    else          { ((ushort4*)g_f1hi)[i4] = hv; ((ushort4*)g_f1lo)[i4] = lv; }
}

// ---------------- small-J heads (fp32 warp dots, float4) ----------------
__global__ void smalldot(int asel, const float* __restrict__ Wt, const float* __restrict__ bias,
                         float* outp, int K, int J){
    const float* A = (asel == 0) ? g_h2 : g_f2;
    float* O = outp ? outp : g_off;
    int m    = blockIdx.x;
    int warp = threadIdx.x >> 5;
    int lane = threadIdx.x & 31;
    const float4* a = (const float4*)(A + (size_t)m*K);
    int K4 = K >> 2;
    for (int j = warp; j < J; j += 8){
        const float4* w = (const float4*)(Wt + (size_t)j*K);
        float s = 0.f;
        for (int k = lane; k < K4; k += 32){
            float4 av = a[k], wv = w[k];
            s += av.x*wv.x + av.y*wv.y + av.z*wv.z + av.w*wv.w;
        }
        #pragma unroll
        for (int o = 16; o; o >>= 1) s += __shfl_xor_sync(0xffffffffu, s, o);
        if (lane == 0) O[m*J + j] = s + bias[j];
    }
}

// ---------------- launch ----------------
extern "C" void kernel_launch(void* const* d_in, const int* in_sizes, int n_in,
                              void* d_out, int out_size){
    const float* x    = (const float*)d_in[0];
    const float* rois = (const float*)d_in[1];
    const float* ow1  = (const float*)d_in[2];
    const float* ob1  = (const float*)d_in[3];
    const float* ow2  = (const float*)d_in[4];
    const float* ob2  = (const float*)d_in[5];
    const float* ow3  = (const float*)d_in[6];
    const float* ob3  = (const float*)d_in[7];
    const float* f1w  = (const float*)d_in[8];
    const float* f1b  = (const float*)d_in[9];
    const float* f2w  = (const float*)d_in[10];
    const float* f2b  = (const float*)d_in[11];
    const float* bxw  = (const float*)d_in[12];
    const float* bxb  = (const float*)d_in[13];

    cudaFuncSetAttribute(gemm_mma, cudaFuncAttributeMaxDynamicSharedMemorySize, GSMEM);
    cudaFuncSetAttribute(gemm_f16, cudaFuncAttributeMaxDynamicSharedMemorySize, GSMEM_F16);

    __half *w1f, *fw1f;
    __nv_bfloat16 *w2hi, *w2lo, *fw2hi, *fw2lo;
    cudaGetSymbolAddress((void**)&w1f,  g_w1f);   cudaGetSymbolAddress((void**)&fw1f, g_fw1f);
    cudaGetSymbolAddress((void**)&w2hi, g_w2hi);  cudaGetSymbolAddress((void**)&w2lo, g_w2lo);
    cudaGetSymbolAddress((void**)&fw2hi,g_fw2hi); cudaGetSymbolAddress((void**)&fw2lo,g_fw2lo);

    nchw2nhwc<<<BIMG*HH*WW, CCH>>>(x);

    convw_f16<<<(DFC*KIN/4 + 255)/256, 256>>>(ow1, w1f,  DFC*KIN/4);
    convw_f16<<<(FCC*KIN/4 + 255)/256, 256>>>(f1w, fw1f, FCC*KIN/4);
    convw<<<(DFC*DFC/4 + 255)/256, 256>>>(ow2, w2hi, w2lo, DFC*DFC/4);
    convw<<<(FCC*FCC/4 + 255)/256, 256>>>(f2w, fw2hi, fw2lo, FCC*FCC/4);

    pool_kernel<<<dim3(N_ROIS,2), 256>>>(rois, 0);

    // h1 = relu(p @ ow1^T + b1)  [256x1024], K=12544 (392 chunks): SK=14, cpz=28
    gemm_f16<<<dim3(8,2,14), 256, GSMEM_F16>>>(w1f, KIN, DFC, 28);
    reduce_bias_relu<<<(N_ROIS*DFC/4)/256, 256>>>(0, ob1, N_ROIS*DFC, DFC, 14);

    // h2 = relu(h1 @ ow2^T + b2)  K=1024 (32 chunks): SK=16, cpz=2
    gemm_mma<<<dim3(8,2,16), 256, GSMEM>>>(1, w2hi, w2lo, DFC, DFC, 2);
    reduce_bias_relu<<<(N_ROIS*DFC/4)/256, 256>>>(1, ob2, N_ROIS*DFC, DFC, 16);

    // off = h2 @ ow3^T + b3  [256x98]
    smalldot<<<N_ROIS, 256>>>(0, ow3, ob3, nullptr, DFC, 98);

    pool_kernel<<<dim3(N_ROIS,2), 256>>>(rois, 1);

    // f1 = relu(p @ f1w^T + b)  [256x512], K=12544 (392 chunks): SK=28, cpz=14
    gemm_f16<<<dim3(4,2,28), 256, GSMEM_F16>>>(fw1f, KIN, FCC, 14);
    reduce_bias_relu<<<(N_ROIS*FCC/4)/256, 256>>>(2, f1b, N_ROIS*FCC, FCC, 28);

    // f2 = relu(f1 @ f2w^T + b)  K=512 (16 chunks): SK=16, cpz=1
    gemm_mma<<<dim3(4,2,16), 256, GSMEM>>>(2, fw2hi, fw2lo, FCC, FCC, 1);
    reduce_bias_relu<<<(N_ROIS*FCC/4)/256, 256>>>(3, f2b, N_ROIS*FCC, FCC, 16);

    // out = f2 @ box_w^T + box_b  [256x4]
    smalldot<<<N_ROIS, 256>>>(1, bxw, bxb, (float*)d_out, FCC, 4);
}

// round 15
// speedup vs baseline: 2.0852x; 1.3854x over previous
#include <cuda_runtime.h>
#include <cuda_bf16.h>
#include <cuda_fp16.h>
#include <cstdint>

// Problem constants
#define N_ROIS 256
#define CCH    256
#define HH     25
#define WW     25
#define BIMG   8
#define KIN    12544   // 256*49
#define DFC    1024
#define FCC    512
#define SSC    (25.0f/255.0f)

// ---------------- scratch (static device globals; no allocs) ----------------
__device__ __align__(256) float g_xt[BIMG*HH*WW*CCH];        // NHWC feature map
__device__ __align__(256) __half g_pa  [N_ROIS*KIN];         // pooled fp16 (single)
__device__ __align__(256) __half g_h1hi[N_ROIS*DFC];
__device__ __align__(256) __half g_h1lo[N_ROIS*DFC];
__device__ __align__(256) float  g_h2[N_ROIS*DFC];
__device__ __align__(256) __half g_f1hi[N_ROIS*FCC];
__device__ __align__(256) __half g_f1lo[N_ROIS*FCC];
__device__ __align__(256) float  g_f2[N_ROIS*FCC];
__device__ __align__(256) float  g_off[N_ROIS*98];
__device__ __align__(256) float  g_part[5*1024*1024];
// converted weights (single fp16)
__device__ __align__(256) __half g_w1f [DFC*KIN];
__device__ __align__(256) __half g_w2f [DFC*DFC];
__device__ __align__(256) __half g_fw1f[FCC*KIN];
__device__ __align__(256) __half g_fw2f[FCC*FCC];

// ---------------- helpers ----------------
__device__ __forceinline__ uint32_t smem_u32(const void* p){
    uint32_t a;
    asm("{ .reg .u64 t; cvta.to.shared.u64 t, %1; cvt.u32.u64 %0, t; }" : "=r"(a) : "l"(p));
    return a;
}
#define CP_ASYNC16(dst, src) \
    asm volatile("cp.async.cg.shared.global [%0], [%1], 16;" :: "r"(dst), "l"(src) : "memory")
#define CP_COMMIT() asm volatile("cp.async.commit_group;" ::: "memory")
#define CP_WAIT2()  asm volatile("cp.async.wait_group 2;" ::: "memory")
#define CP_WAIT1()  asm volatile("cp.async.wait_group 1;" ::: "memory")
#define CP_WAIT0()  asm volatile("cp.async.wait_group 0;" ::: "memory")

__device__ __forceinline__ void ldm_x4(uint32_t& r0, uint32_t& r1, uint32_t& r2, uint32_t& r3,
                                       uint32_t addr){
    asm volatile("ldmatrix.sync.aligned.m8n8.x4.shared.b16 {%0,%1,%2,%3}, [%4];"
                 : "=r"(r0), "=r"(r1), "=r"(r2), "=r"(r3) : "r"(addr));
}
__device__ __forceinline__ void mma_f16(float* c, uint32_t a0, uint32_t a1, uint32_t a2,
                                        uint32_t a3, uint32_t b0, uint32_t b1){
    asm volatile("mma.sync.aligned.m16n8k16.row.col.f32.f16.f16.f32 "
                 "{%0,%1,%2,%3}, {%4,%5,%6,%7}, {%8,%9}, {%0,%1,%2,%3};"
                 : "+f"(c[0]), "+f"(c[1]), "+f"(c[2]), "+f"(c[3])
                 : "r"(a0), "r"(a1), "r"(a2), "r"(a3), "r"(b0), "r"(b1));
}

// ---------------- NCHW -> NHWC transpose ----------------
__global__ void nchw2nhwc(const float* __restrict__ x){
    int pidx = blockIdx.x;
    int c    = threadIdx.x;
    int b  = pidx / (HH*WW);
    int hw = pidx - b*(HH*WW);
    g_xt[(b*(HH*WW) + hw)*CCH + c] = x[(b*CCH + c)*(HH*WW) + hw];
}

// ---------------- fp32 -> fp16 single weight conversion ----------------
__global__ void convw_f16(const float* __restrict__ s, __half* __restrict__ o, int n4){
    int i = blockIdx.x*256 + threadIdx.x;
    if (i >= n4) return;
    float4 v = ((const float4*)s)[i];
    __half h0 = __float2half(v.x), h1 = __float2half(v.y);
    __half h2 = __float2half(v.z), h3 = __float2half(v.w);
    ushort4 hv = make_ushort4(*(unsigned short*)&h0, *(unsigned short*)&h1,
                              *(unsigned short*)&h2, *(unsigned short*)&h3);
    ((ushort4*)o)[i] = hv;
}

// ---------------- deformable ROI pool (writes single fp16 pooled features) ----------------
__global__ void __launch_bounds__(256) pool_kernel(const float* __restrict__ rois, int use_off){
    int n    = blockIdx.x;
    int half = blockIdx.y;
    int tid  = threadIdx.x;
    int cg   = ((tid & 31) << 2) + half*128;
    int bs   = tid >> 5;

    const float* r = rois + n*5;
    int   b  = (int)r[0];
    float sw = rintf(r[1])*SSC - 0.5f;
    float sh = rintf(r[2])*SSC - 0.5f;
    float rw = fmaxf((rintf(r[3]) + 1.0f)*SSC - 0.5f - sw, 0.1f);
    float rh = fmaxf((rintf(r[4]) + 1.0f)*SSC - 0.5f - sh, 0.1f);
    float bw = rw / 7.0f, bh = rh / 7.0f;
    float bwq = bw*0.25f, bhq = bh*0.25f;

    for(int bin = bs; bin < 49; bin += 8){
        int ph = bin / 7, pw = bin - ph*7;
        float tx = use_off ? g_off[n*98 + bin]      * 0.1f : 0.0f;
        float ty = use_off ? g_off[n*98 + 49 + bin] * 0.1f : 0.0f;
        float wst = pw*bw + sw + tx*rw;
        float hst = ph*bh + sh + ty*rh;

        float ax=0.f, ay=0.f, az=0.f, aw=0.f;
        int cnt = 0;
        #pragma unroll
        for(int iy=0; iy<4; iy++){
            float sy = hst + iy*bhq;
            bool  vy = (sy >= -0.5f) && (sy <= (float)HH - 0.5f);
            float yc  = fminf(fmaxf(sy, 0.0f), (float)(HH-1));
            float y0f = floorf(yc);
            float dy  = yc - y0f;
            int yi0 = (int)y0f;
            int yi1 = (int)ceilf(yc);
            #pragma unroll
            for(int ix=0; ix<4; ix++){
                float sx = wst + ix*bwq;
                if(!vy || sx < -0.5f || sx > (float)WW - 0.5f) continue;
                cnt++;
                float xc  = fminf(fmaxf(sx, 0.0f), (float)(WW-1));
                float x0f = floorf(xc);
                float dx  = xc - x0f;
                int xi0 = (int)x0f;
                int xi1 = (int)ceilf(xc);
                int rb0 = (b*HH + yi0)*WW;
                int rb1 = (b*HH + yi1)*WW;
                float4 v00 = *(const float4*)(g_xt + (rb0 + xi0)*CCH + cg);
                float4 v01 = *(const float4*)(g_xt + (rb0 + xi1)*CCH + cg);
                float4 v10 = *(const float4*)(g_xt + (rb1 + xi0)*CCH + cg);
                float4 v11 = *(const float4*)(g_xt + (rb1 + xi1)*CCH + cg);
                float w00 = (1.f-dx)*(1.f-dy), w01 = dx*(1.f-dy);
                float w10 = (1.f-dx)*dy,       w11 = dx*dy;
                ax += w00*v00.x + w01*v01.x + w10*v10.x + w11*v11.x;
                ay += w00*v00.y + w01*v01.y + w10*v10.y + w11*v11.y;
                az += w00*v00.z + w01*v01.z + w10*v10.z + w11*v11.z;
                aw += w00*v00.w + w01*v01.w + w10*v10.w + w11*v11.w;
            }
        }
        float inv = 1.0f / fmaxf((float)cnt, 1.0f);
        int idx = n*KIN + cg*49 + bin;   // layout matches reshape: c*49 + bin
        g_pa[idx]     = __float2half(ax*inv);
        g_pa[idx+49]  = __float2half(ay*inv);
        g_pa[idx+98]  = __float2half(az*inv);
        g_pa[idx+147] = __float2half(aw*inv);
    }
}

// ================= fp16 split-K GEMM, NP passes (NP=1: A single; NP=2: A hi+lo) =================
// C = A @ W^T. CTA tile 128x128, BK=32, 8 warps (4x2, 32x64 each), 3-stage cp.async.
#define BM 128
#define BN 128
#define BK 32
#define ROWB 80                 // padded row bytes (32 x 2B = 64B + 16B pad)

template<int NP>
__global__ void __launch_bounds__(256)
gemm_f16(const __half* __restrict__ Ah, const __half* __restrict__ Al,
         const __half* __restrict__ Wf, int K, int J, int cpz){
    constexpr int A_HI = 0;
    constexpr int A_LO = BM*ROWB;              // valid when NP==2
    constexpr int W_OFF = NP*BM*ROWB;
    constexpr int STG  = (NP+1)*BM*ROWB;       // 20480 (NP=1) / 30720 (NP=2)

    extern __shared__ char smem[];
    uint32_t sb = smem_u32(smem);
    int jt  = blockIdx.x*BN;
    int mt  = blockIdx.y*BM;
    int z   = blockIdx.z;
    int tid = threadIdx.x, wid = tid >> 5, lane = tid & 31;
    int wm = wid >> 1, wn = wid & 1;   // 4 x 2 warps (32 rows x 64 cols)

    // loaders: 128 rows x 4 segs of 16B, 2 adjacent segs per thread
    int lrow0 = tid >> 1, lseg0 = (tid & 1) << 1;
    size_t kstep = (size_t)z*cpz*BK*2;
    const char* gAh = (const char*)(Ah) + ((size_t)(mt + lrow0)*K + (size_t)lseg0*8)*2 + kstep;
    const char* gAl = (NP == 2) ? (const char*)(Al) + ((size_t)(mt + lrow0)*K + (size_t)lseg0*8)*2 + kstep : nullptr;
    const char* gW  = (const char*)(Wf) + ((size_t)(jt + lrow0)*K + (size_t)lseg0*8)*2 + kstep;
    uint32_t dst = sb + lrow0*ROWB + lseg0*16;

    uint32_t lrow = lane & 15;
    uint32_t lcol = (lane >> 4) << 4;
    uint32_t aA0 = (wm*32 + 0  + lrow)*ROWB + lcol;
    uint32_t aA1 = (wm*32 + 16 + lrow)*ROWB + lcol;
    uint32_t aW[4];
    #pragma unroll
    for (int p = 0; p < 4; p++) aW[p] = (wn*64 + p*16 + lrow)*ROWB + lcol;

    float acc[2][8][4];
    #pragma unroll
    for (int t = 0; t < 2; t++)
        #pragma unroll
        for (int u = 0; u < 8; u++)
            #pragma unroll
            for (int q = 0; q < 4; q++) acc[t][u][q] = 0.f;

    // prologue: issue chunks 0 and 1
    {
        CP_ASYNC16(dst + A_HI,      gAh);
        CP_ASYNC16(dst + A_HI + 16, gAh + 16);
        if (NP == 2){
            CP_ASYNC16(dst + A_LO,      gAl);
            CP_ASYNC16(dst + A_LO + 16, gAl + 16);
        }
        CP_ASYNC16(dst + W_OFF,      gW);
        CP_ASYNC16(dst + W_OFF + 16, gW + 16);
        CP_COMMIT();
    }
    if (cpz > 1){
        size_t off = (size_t)BK*2;
        uint32_t ns = dst + STG;
        CP_ASYNC16(ns + A_HI,      gAh + off);
        CP_ASYNC16(ns + A_HI + 16, gAh + off + 16);
        if (NP == 2){
            CP_ASYNC16(ns + A_LO,      gAl + off);
            CP_ASYNC16(ns + A_LO + 16, gAl + off + 16);
        }
        CP_ASYNC16(ns + W_OFF,      gW + off);
        CP_ASYNC16(ns + W_OFF + 16, gW + off + 16);
        CP_COMMIT();
    }

    for (int c = 0; c < cpz; c++){
        if (c + 2 < cpz){
            size_t off = (size_t)(c + 2)*BK*2;
            uint32_t ns = dst + ((c + 2) % 3)*STG;
            CP_ASYNC16(ns + A_HI,      gAh + off);
            CP_ASYNC16(ns + A_HI + 16, gAh + off + 16);
            if (NP == 2){
                CP_ASYNC16(ns + A_LO,      gAl + off);
                CP_ASYNC16(ns + A_LO + 16, gAl + off + 16);
            }
            CP_ASYNC16(ns + W_OFF,      gW + off);
            CP_ASYNC16(ns + W_OFF + 16, gW + off + 16);
            CP_COMMIT();
            CP_WAIT2();
        } else if (c + 1 < cpz){
            CP_WAIT1();
        } else {
            CP_WAIT0();
        }
        __syncthreads();

        uint32_t cs = (c % 3)*STG;
        #pragma unroll
        for (int ks = 0; ks < 2; ks++){
            uint32_t kb = cs + ks*32;
            uint32_t ah[2][4], al[2][4], wh[4][4];
            ldm_x4(ah[0][0], ah[0][1], ah[0][2], ah[0][3], sb + A_HI + kb + aA0);
            ldm_x4(ah[1][0], ah[1][1], ah[1][2], ah[1][3], sb + A_HI + kb + aA1);
            if (NP == 2){
                ldm_x4(al[0][0], al[0][1], al[0][2], al[0][3], sb + A_LO + kb + aA0);
                ldm_x4(al[1][0], al[1][1], al[1][2], al[1][3], sb + A_LO + kb + aA1);
            }
            #pragma unroll
            for (int p = 0; p < 4; p++)
                ldm_x4(wh[p][0], wh[p][1], wh[p][2], wh[p][3], sb + W_OFF + kb + aW[p]);
            #pragma unroll
            for (int t = 0; t < 2; t++){
                #pragma unroll
                for (int u = 0; u < 8; u++){
                    int p = u >> 1, s = u & 1;
                    uint32_t b0 = wh[p][s], b1 = wh[p][s+2];
                    mma_f16(acc[t][u], ah[t][0], ah[t][1], ah[t][2], ah[t][3], b0, b1);
                    if (NP == 2)
                        mma_f16(acc[t][u], al[t][0], al[t][1], al[t][2], al[t][3], b0, b1);
                }
            }
        }
        __syncthreads();
    }

    int gmb = mt + wm*32;
    int gjb = jt + wn*64;
    int r0 = lane >> 2, c0 = (lane & 3) << 1;
    #pragma unroll
    for (int t = 0; t < 2; t++){
        #pragma unroll
        for (int u = 0; u < 8; u++){
            int gm = gmb + t*16 + r0;
            int gj = gjb + u*8 + c0;
            float2 lo = make_float2(acc[t][u][0], acc[t][u][1]);
            float2 hi = make_float2(acc[t][u][2], acc[t][u][3]);
            *(float2*)(g_part + ((size_t)z*N_ROIS + gm    )*J + gj) = lo;
            *(float2*)(g_part + ((size_t)z*N_ROIS + gm + 8)*J + gj) = hi;
        }
    }
}

// ---------------- split-K reduction + bias + relu (+ fp16 hi/lo conversion), float4 ----------------
__global__ void reduce_bias_relu(int osel, const float* __restrict__ bias, int MJ, int J, int SK){
    int i4 = blockIdx.x*256 + threadIdx.x;       // float4 index
    if (i4 >= MJ/4) return;
    int MJ4 = MJ >> 2;
    float4 s = ((const float4*)g_part)[i4];
    for (int zz = 1; zz < SK; zz++){
        float4 p = ((const float4*)g_part)[(size_t)zz*MJ4 + i4];
        s.x += p.x; s.y += p.y; s.z += p.z; s.w += p.w;
    }
    float4 bv = ((const float4*)bias)[i4 % (J >> 2)];
    s.x = fmaxf(s.x + bv.x, 0.f);
    s.y = fmaxf(s.y + bv.y, 0.f);
    s.z = fmaxf(s.z + bv.z, 0.f);
    s.w = fmaxf(s.w + bv.w, 0.f);
    if (osel == 1){ ((float4*)g_h2)[i4] = s; return; }
    if (osel == 3){ ((float4*)g_f2)[i4] = s; return; }
    __half h0 = __float2half(s.x), h1 = __float2half(s.y);
    __half h2 = __float2half(s.z), h3 = __float2half(s.w);
    __half l0 = __float2half(s.x - __half2float(h0));
    __half l1 = __float2half(s.y - __half2float(h1));
    __half l2 = __float2half(s.z - __half2float(h2));
    __half l3 = __float2half(s.w - __half2float(h3));
    ushort4 hv = make_ushort4(*(unsigned short*)&h0, *(unsigned short*)&h1,
                              *(unsigned short*)&h2, *(unsigned short*)&h3);
    ushort4 lv = make_ushort4(*(unsigned short*)&l0, *(unsigned short*)&l1,
                              *(unsigned short*)&l2, *(unsigned short*)&l3);
    if (osel == 0){ ((ushort4*)g_h1hi)[i4] = hv; ((ushort4*)g_h1lo)[i4] = lv; }
    else          { ((ushort4*)g_f1hi)[i4] = hv; ((ushort4*)g_f1lo)[i4] = lv; }
}

// ---------------- small-J heads (fp32 warp dots, float4) ----------------
__global__ void smalldot(int asel, const float* __restrict__ Wt, const float* __restrict__ bias,
                         float* outp, int K, int J){
    const float* A = (asel == 0) ? g_h2 : g_f2;
    float* O = outp ? outp : g_off;
    int m    = blockIdx.x;
    int warp = threadIdx.x >> 5;
    int lane = threadIdx.x & 31;
    const float4* a = (const float4*)(A + (size_t)m*K);
    int K4 = K >> 2;
    for (int j = warp; j < J; j += 8){
        const float4* w = (const float4*)(Wt + (size_t)j*K);
        float s = 0.f;
        for (int k = lane; k < K4; k += 32){
            float4 av = a[k], wv = w[k];
            s += av.x*wv.x + av.y*wv.y + av.z*wv.z + av.w*wv.w;
        }
        #pragma unroll
        for (int o = 16; o; o >>= 1) s += __shfl_xor_sync(0xffffffffu, s, o);
        if (lane == 0) O[m*J + j] = s + bias[j];
    }
}

// ---------------- launch ----------------
extern "C" void kernel_launch(void* const* d_in, const int* in_sizes, int n_in,
                              void* d_out, int out_size){
    const float* x    = (const float*)d_in[0];
    const float* rois = (const float*)d_in[1];
    const float* ow1  = (const float*)d_in[2];
    const float* ob1  = (const float*)d_in[3];
    const float* ow2  = (const float*)d_in[4];
    const float* ob2  = (const float*)d_in[5];
    const float* ow3  = (const float*)d_in[6];
    const float* ob3  = (const float*)d_in[7];
    const float* f1w  = (const float*)d_in[8];
    const float* f1b  = (const float*)d_in[9];
    const float* f2w  = (const float*)d_in[10];
    const float* f2b  = (const float*)d_in[11];
    const float* bxw  = (const float*)d_in[12];
    const float* bxb  = (const float*)d_in[13];

    cudaFuncSetAttribute(gemm_f16<1>, cudaFuncAttributeMaxDynamicSharedMemorySize, 3*2*BM*ROWB);
    cudaFuncSetAttribute(gemm_f16<2>, cudaFuncAttributeMaxDynamicSharedMemorySize, 3*3*BM*ROWB);

    __half *w1f, *w2f, *fw1f, *fw2f, *h1hi, *h1lo, *f1hi, *f1lo;
    cudaGetSymbolAddress((void**)&w1f,  g_w1f);   cudaGetSymbolAddress((void**)&w2f,  g_w2f);
    cudaGetSymbolAddress((void**)&fw1f, g_fw1f);  cudaGetSymbolAddress((void**)&fw2f, g_fw2f);
    cudaGetSymbolAddress((void**)&h1hi, g_h1hi);  cudaGetSymbolAddress((void**)&h1lo, g_h1lo);
    cudaGetSymbolAddress((void**)&f1hi, g_f1hi);  cudaGetSymbolAddress((void**)&f1lo, g_f1lo);
    __half *paf;
    cudaGetSymbolAddress((void**)&paf, g_pa);

    // 1
    nchw2nhwc<<<BIMG*HH*WW, CCH>>>(x);
    // 2
    convw_f16<<<(DFC*KIN/4 + 255)/256, 256>>>(ow1, w1f, DFC*KIN/4);
    // 3
    pool_kernel<<<dim3(N_ROIS,2), 256>>>(rois, 0);
    // 4: h1 = relu(p @ ow1^T + b1)  [256x1024], 392 chunks: SK=14, cpz=28  (ncu capture target)
    gemm_f16<1><<<dim3(8,2,14), 256, 3*2*BM*ROWB>>>(paf, nullptr, w1f, KIN, DFC, 28);
    // 5
    reduce_bias_relu<<<(N_ROIS*DFC/4)/256, 256>>>(0, ob1, N_ROIS*DFC, DFC, 14);
    // 6
    convw_f16<<<(DFC*DFC/4 + 255)/256, 256>>>(ow2, w2f, DFC*DFC/4);
    // 7: h2 = relu(h1 @ ow2^T + b2)  K=1024 (32 chunks): SK=16, cpz=2
    gemm_f16<2><<<dim3(8,2,16), 256, 3*3*BM*ROWB>>>(h1hi, h1lo, w2f, DFC, DFC, 2);
    // 8
    reduce_bias_relu<<<(N_ROIS*DFC/4)/256, 256>>>(1, ob2, N_ROIS*DFC, DFC, 16);
    // 9
    smalldot<<<N_ROIS, 256>>>(0, ow3, ob3, nullptr, DFC, 98);
    // 10
    pool_kernel<<<dim3(N_ROIS,2), 256>>>(rois, 1);
    // 11
    convw_f16<<<(FCC*KIN/4 + 255)/256, 256>>>(f1w, fw1f, FCC*KIN/4);
    // 12: f1 = relu(p @ f1w^T + b)  [256x512], 392 chunks: SK=28, cpz=14
    gemm_f16<1><<<dim3(4,2,28), 256, 3*2*BM*ROWB>>>(paf, nullptr, fw1f, KIN, FCC, 14);
    // 13
    reduce_bias_relu<<<(N_ROIS*FCC/4)/256, 256>>>(2, f1b, N_ROIS*FCC, FCC, 28);
    // 14
    convw_f16<<<(FCC*FCC/4 + 255)/256, 256>>>(f2w, fw2f, FCC*FCC/4);
    // 15: f2 = relu(f1 @ f2w^T + b)  K=512 (16 chunks): SK=16, cpz=1
    gemm_f16<2><<<dim3(4,2,16), 256, 3*3*BM*ROWB>>>(f1hi, f1lo, fw2f, FCC, FCC, 1);
    // 16
    reduce_bias_relu<<<(N_ROIS*FCC/4)/256, 256>>>(3, f2b, N_ROIS*FCC, FCC, 16);
    // 17
    smalldot<<<N_ROIS, 256>>>(1, bxw, bxb, (float*)d_out, FCC, 4);
}

// round 16
// speedup vs baseline: 2.1162x; 1.0148x over previous
#include <cuda_runtime.h>
#include <cuda_bf16.h>
#include <cuda_fp16.h>
#include <cstdint>

// Problem constants
#define N_ROIS 256
#define CCH    256
#define HH     25
#define WW     25
#define BIMG   8
#define KIN    12544   // 256*49
#define DFC    1024
#define FCC    512
#define SSC    (25.0f/255.0f)

// ---------------- scratch (static device globals; no allocs) ----------------
__device__ __align__(256) float g_xt[BIMG*HH*WW*CCH];        // NHWC feature map
__device__ __align__(256) __half g_pa  [N_ROIS*KIN];         // pooled fp16 (single)
__device__ __align__(256) __half g_h1hi[N_ROIS*DFC];
__device__ __align__(256) __half g_h1lo[N_ROIS*DFC];
__device__ __align__(256) float  g_h2[N_ROIS*DFC];
__device__ __align__(256) __half g_f1hi[N_ROIS*FCC];
__device__ __align__(256) __half g_f1lo[N_ROIS*FCC];
__device__ __align__(256) float  g_f2[N_ROIS*FCC];
__device__ __align__(256) float  g_off[N_ROIS*98];
__device__ __align__(256) float  g_part[8*1024*1024];        // split-K partials (32 MB)
// converted weights (single fp16)
__device__ __align__(256) __half g_w1f [DFC*KIN];
__device__ __align__(256) __half g_w2f [DFC*DFC];
__device__ __align__(256) __half g_fw1f[FCC*KIN];
__device__ __align__(256) __half g_fw2f[FCC*FCC];

// ---------------- helpers ----------------
__device__ __forceinline__ uint32_t smem_u32(const void* p){
    uint32_t a;
    asm("{ .reg .u64 t; cvta.to.shared.u64 t, %1; cvt.u32.u64 %0, t; }" : "=r"(a) : "l"(p));
    return a;
}
#define CP_ASYNC16(dst, src) \
    asm volatile("cp.async.cg.shared.global [%0], [%1], 16;" :: "r"(dst), "l"(src) : "memory")
#define CP_COMMIT() asm volatile("cp.async.commit_group;" ::: "memory")
#define CP_WAIT1()  asm volatile("cp.async.wait_group 1;" ::: "memory")
#define CP_WAIT0()  asm volatile("cp.async.wait_group 0;" ::: "memory")

__device__ __forceinline__ void ldm_x4(uint32_t& r0, uint32_t& r1, uint32_t& r2, uint32_t& r3,
                                       uint32_t addr){
    asm volatile("ldmatrix.sync.aligned.m8n8.x4.shared.b16 {%0,%1,%2,%3}, [%4];"
                 : "=r"(r0), "=r"(r1), "=r"(r2), "=r"(r3) : "r"(addr));
}
__device__ __forceinline__ void mma_f16(float* c, uint32_t a0, uint32_t a1, uint32_t a2,
                                        uint32_t a3, uint32_t b0, uint32_t b1){
    asm volatile("mma.sync.aligned.m16n8k16.row.col.f32.f16.f16.f32 "
                 "{%0,%1,%2,%3}, {%4,%5,%6,%7}, {%8,%9}, {%0,%1,%2,%3};"
                 : "+f"(c[0]), "+f"(c[1]), "+f"(c[2]), "+f"(c[3])
                 : "r"(a0), "r"(a1), "r"(a2), "r"(a3), "r"(b0), "r"(b1));
}

// ---------------- NCHW -> NHWC transpose ----------------
__global__ void nchw2nhwc(const float* __restrict__ x){
    int pidx = blockIdx.x;
    int c    = threadIdx.x;
    int b  = pidx / (HH*WW);
    int hw = pidx - b*(HH*WW);
    g_xt[(b*(HH*WW) + hw)*CCH + c] = x[(b*CCH + c)*(HH*WW) + hw];
}

// ---------------- fp32 -> fp16 single weight conversion ----------------
__global__ void convw_f16(const float* __restrict__ s, __half* __restrict__ o, int n4){
    int i = blockIdx.x*256 + threadIdx.x;
    if (i >= n4) return;
    float4 v = ((const float4*)s)[i];
    __half h0 = __float2half(v.x), h1 = __float2half(v.y);
    __half h2 = __float2half(v.z), h3 = __float2half(v.w);
    ushort4 hv = make_ushort4(*(unsigned short*)&h0, *(unsigned short*)&h1,
                              *(unsigned short*)&h2, *(unsigned short*)&h3);
    ((ushort4*)o)[i] = hv;
}

// ---------------- deformable ROI pool (writes single fp16 pooled features) ----------------
__global__ void __launch_bounds__(256) pool_kernel(const float* __restrict__ rois, int use_off){
    int n    = blockIdx.x;
    int half = blockIdx.y;
    int tid  = threadIdx.x;
    int cg   = ((tid & 31) << 2) + half*128;
    int bs   = tid >> 5;

    const float* r = rois + n*5;
    int   b  = (int)r[0];
    float sw = rintf(r[1])*SSC - 0.5f;
    float sh = rintf(r[2])*SSC - 0.5f;
    float rw = fmaxf((rintf(r[3]) + 1.0f)*SSC - 0.5f - sw, 0.1f);
    float rh = fmaxf((rintf(r[4]) + 1.0f)*SSC - 0.5f - sh, 0.1f);
    float bw = rw / 7.0f, bh = rh / 7.0f;
    float bwq = bw*0.25f, bhq = bh*0.25f;

    for(int bin = bs; bin < 49; bin += 8){
        int ph = bin / 7, pw = bin - ph*7;
        float tx = use_off ? g_off[n*98 + bin]      * 0.1f : 0.0f;
        float ty = use_off ? g_off[n*98 + 49 + bin] * 0.1f : 0.0f;
        float wst = pw*bw + sw + tx*rw;
        float hst = ph*bh + sh + ty*rh;

        float ax=0.f, ay=0.f, az=0.f, aw=0.f;
        int cnt = 0;
        #pragma unroll
        for(int iy=0; iy<4; iy++){
            float sy = hst + iy*bhq;
            bool  vy = (sy >= -0.5f) && (sy <= (float)HH - 0.5f);
            float yc  = fminf(fmaxf(sy, 0.0f), (float)(HH-1));
            float y0f = floorf(yc);
            float dy  = yc - y0f;
            int yi0 = (int)y0f;
            int yi1 = (int)ceilf(yc);
            #pragma unroll
            for(int ix=0; ix<4; ix++){
                float sx = wst + ix*bwq;
                if(!vy || sx < -0.5f || sx > (float)WW - 0.5f) continue;
                cnt++;
                float xc  = fminf(fmaxf(sx, 0.0f), (float)(WW-1));
                float x0f = floorf(xc);
                float dx  = xc - x0f;
                int xi0 = (int)x0f;
                int xi1 = (int)ceilf(xc);
                int rb0 = (b*HH + yi0)*WW;
                int rb1 = (b*HH + yi1)*WW;
                float4 v00 = *(const float4*)(g_xt + (rb0 + xi0)*CCH + cg);
                float4 v01 = *(const float4*)(g_xt + (rb0 + xi1)*CCH + cg);
                float4 v10 = *(const float4*)(g_xt + (rb1 + xi0)*CCH + cg);
                float4 v11 = *(const float4*)(g_xt + (rb1 + xi1)*CCH + cg);
                float w00 = (1.f-dx)*(1.f-dy), w01 = dx*(1.f-dy);
                float w10 = (1.f-dx)*dy,       w11 = dx*dy;
                ax += w00*v00.x + w01*v01.x + w10*v10.x + w11*v11.x;
                ay += w00*v00.y + w01*v01.y + w10*v10.y + w11*v11.y;
                az += w00*v00.z + w01*v01.z + w10*v10.z + w11*v11.z;
                aw += w00*v00.w + w01*v01.w + w10*v10.w + w11*v11.w;
            }
        }
        float inv = 1.0f / fmaxf((float)cnt, 1.0f);
        int idx = n*KIN + cg*49 + bin;   // layout matches reshape: c*49 + bin
        g_pa[idx]     = __float2half(ax*inv);
        g_pa[idx+49]  = __float2half(ay*inv);
        g_pa[idx+98]  = __float2half(az*inv);
        g_pa[idx+147] = __float2half(aw*inv);
    }
}

// ================= fp16 split-K GEMM, NP passes, 2-stage cp.async =================
// C = A @ W^T. CTA tile 128x128, BK=32, 8 warps (4x2, 32x64 each).
#define BM 128
#define BN 128
#define BK 32
#define ROWB 80                 // padded row bytes (32 x 2B = 64B + 16B pad)

template<int NP>
__global__ void __launch_bounds__(256)
gemm_f16(const __half* __restrict__ Ah, const __half* __restrict__ Al,
         const __half* __restrict__ Wf, int K, int J, int cpz){
    constexpr int A_HI = 0;
    constexpr int A_LO = BM*ROWB;              // valid when NP==2
    constexpr int W_OFF = NP*BM*ROWB;
    constexpr int STG  = (NP+1)*BM*ROWB;       // 20480 (NP=1) / 30720 (NP=2)

    extern __shared__ char smem[];
    uint32_t sb = smem_u32(smem);
    int jt  = blockIdx.x*BN;
    int mt  = blockIdx.y*BM;
    int z   = blockIdx.z;
    int tid = threadIdx.x, wid = tid >> 5, lane = tid & 31;
    int wm = wid >> 1, wn = wid & 1;   // 4 x 2 warps (32 rows x 64 cols)

    // loaders: 128 rows x 4 segs of 16B, 2 adjacent segs per thread
    int lrow0 = tid >> 1, lseg0 = (tid & 1) << 1;
    size_t kstep = (size_t)z*cpz*BK*2;
    const char* gAh = (const char*)(Ah) + ((size_t)(mt + lrow0)*K + (size_t)lseg0*8)*2 + kstep;
    const char* gAl = (NP == 2) ? (const char*)(Al) + ((size_t)(mt + lrow0)*K + (size_t)lseg0*8)*2 + kstep : nullptr;
    const char* gW  = (const char*)(Wf) + ((size_t)(jt + lrow0)*K + (size_t)lseg0*8)*2 + kstep;
    uint32_t dst = sb + lrow0*ROWB + lseg0*16;

    uint32_t lrow = lane & 15;
    uint32_t lcol = (lane >> 4) << 4;
    uint32_t aA0 = (wm*32 + 0  + lrow)*ROWB + lcol;
    uint32_t aA1 = (wm*32 + 16 + lrow)*ROWB + lcol;
    uint32_t aW[4];
    #pragma unroll
    for (int p = 0; p < 4; p++) aW[p] = (wn*64 + p*16 + lrow)*ROWB + lcol;

    float acc[2][8][4];
    #pragma unroll
    for (int t = 0; t < 2; t++)
        #pragma unroll
        for (int u = 0; u < 8; u++)
            #pragma unroll
            for (int q = 0; q < 4; q++) acc[t][u][q] = 0.f;

    // prologue: load chunk 0 into stage 0
    {
        CP_ASYNC16(dst + A_HI,      gAh);
        CP_ASYNC16(dst + A_HI + 16, gAh + 16);
        if (NP == 2){
            CP_ASYNC16(dst + A_LO,      gAl);
            CP_ASYNC16(dst + A_LO + 16, gAl + 16);
        }
        CP_ASYNC16(dst + W_OFF,      gW);
        CP_ASYNC16(dst + W_OFF + 16, gW + 16);
        CP_COMMIT();
    }

    for (int c = 0; c < cpz; c++){
        if (c + 1 < cpz){
            size_t off = (size_t)(c + 1)*BK*2;
            uint32_t ns = dst + ((c + 1) & 1)*STG;
            CP_ASYNC16(ns + A_HI,      gAh + off);
            CP_ASYNC16(ns + A_HI + 16, gAh + off + 16);
            if (NP == 2){
                CP_ASYNC16(ns + A_LO,      gAl + off);
                CP_ASYNC16(ns + A_LO + 16, gAl + off + 16);
            }
            CP_ASYNC16(ns + W_OFF,      gW + off);
            CP_ASYNC16(ns + W_OFF + 16, gW + off + 16);
            CP_COMMIT();
            CP_WAIT1();
        } else {
            CP_WAIT0();
        }
        __syncthreads();

        uint32_t cs = (c & 1)*STG;
        #pragma unroll
        for (int ks = 0; ks < 2; ks++){
            uint32_t kb = cs + ks*32;
            uint32_t ah[2][4], al[2][4], wh[4][4];
            ldm_x4(ah[0][0], ah[0][1], ah[0][2], ah[0][3], sb + A_HI + kb + aA0);
            ldm_x4(ah[1][0], ah[1][1], ah[1][2], ah[1][3], sb + A_HI + kb + aA1);
            if (NP == 2){
                ldm_x4(al[0][0], al[0][1], al[0][2], al[0][3], sb + A_LO + kb + aA0);
                ldm_x4(al[1][0], al[1][1], al[1][2], al[1][3], sb + A_LO + kb + aA1);
            }
            #pragma unroll
            for (int p = 0; p < 4; p++)
                ldm_x4(wh[p][0], wh[p][1], wh[p][2], wh[p][3], sb + W_OFF + kb + aW[p]);
            #pragma unroll
            for (int t = 0; t < 2; t++){
                #pragma unroll
                for (int u = 0; u < 8; u++){
                    int p = u >> 1, s = u & 1;
                    uint32_t b0 = wh[p][s], b1 = wh[p][s+2];
                    mma_f16(acc[t][u], ah[t][0], ah[t][1], ah[t][2], ah[t][3], b0, b1);
                    if (NP == 2)
                        mma_f16(acc[t][u], al[t][0], al[t][1], al[t][2], al[t][3], b0, b1);
                }
            }
        }
        __syncthreads();
    }

    int gmb = mt + wm*32;
    int gjb = jt + wn*64;
    int r0 = lane >> 2, c0 = (lane & 3) << 1;
    #pragma unroll
    for (int t = 0; t < 2; t++){
        #pragma unroll
        for (int u = 0; u < 8; u++){
            int gm = gmb + t*16 + r0;
            int gj = gjb + u*8 + c0;
            float2 lo = make_float2(acc[t][u][0], acc[t][u][1]);
            float2 hi = make_float2(acc[t][u][2], acc[t][u][3]);
            *(float2*)(g_part + ((size_t)z*N_ROIS + gm    )*J + gj) = lo;
            *(float2*)(g_part + ((size_t)z*N_ROIS + gm + 8)*J + gj) = hi;
        }
    }
}

// ---------------- split-K reduction + bias + relu (+ fp16 hi/lo conversion), float4 ----------------
__global__ void reduce_bias_relu(int osel, const float* __restrict__ bias, int MJ, int J, int SK){
    int i4 = blockIdx.x*256 + threadIdx.x;       // float4 index
    if (i4 >= MJ/4) return;
    int MJ4 = MJ >> 2;
    float4 s = ((const float4*)g_part)[i4];
    for (int zz = 1; zz < SK; zz++){
        float4 p = ((const float4*)g_part)[(size_t)zz*MJ4 + i4];
        s.x += p.x; s.y += p.y; s.z += p.z; s.w += p.w;
    }
    float4 bv = ((const float4*)bias)[i4 % (J >> 2)];
    s.x = fmaxf(s.x + bv.x, 0.f);
    s.y = fmaxf(s.y + bv.y, 0.f);
    s.z = fmaxf(s.z + bv.z, 0.f);
    s.w = fmaxf(s.w + bv.w, 0.f);
    if (osel == 1){ ((float4*)g_h2)[i4] = s; return; }
    if (osel == 3){ ((float4*)g_f2)[i4] = s; return; }
    __half h0 = __float2half(s.x), h1 = __float2half(s.y);
    __half h2 = __float2half(s.z), h3 = __float2half(s.w);
    __half l0 = __float2half(s.x - __half2float(h0));
    __half l1 = __float2half(s.y - __half2float(h1));
    __half l2 = __float2half(s.z - __half2float(h2));
    __half l3 = __float2half(s.w - __half2float(h3));
    ushort4 hv = make_ushort4(*(unsigned short*)&h0, *(unsigned short*)&h1,
                              *(unsigned short*)&h2, *(unsigned short*)&h3);
    ushort4 lv = make_ushort4(*(unsigned short*)&l0, *(unsigned short*)&l1,
                              *(unsigned short*)&l2, *(unsigned short*)&l3);
    if (osel == 0){ ((ushort4*)g_h1hi)[i4] = hv; ((ushort4*)g_h1lo)[i4] = lv; }
    else          { ((ushort4*)g_f1hi)[i4] = hv; ((ushort4*)g_f1lo)[i4] = lv; }
}

// ---------------- small-J heads (fp32 warp dots, float4) ----------------
__global__ void smalldot(int asel, const float* __restrict__ Wt, const float* __restrict__ bias,
                         float* outp, int K, int J){
    const float* A = (asel == 0) ? g_h2 : g_f2;
    float* O = outp ? outp : g_off;
    int m    = blockIdx.x;
    int warp = threadIdx.x >> 5;
    int lane = threadIdx.x & 31;
    const float4* a = (const float4*)(A + (size_t)m*K);
    int K4 = K >> 2;
    for (int j = warp; j < J; j += 8){
        const float4* w = (const float4*)(Wt + (size_t)j*K);
        float s = 0.f;
        for (int k = lane; k < K4; k += 32){
            float4 av = a[k], wv = w[k];
            s += av.x*wv.x + av.y*wv.y + av.z*wv.z + av.w*wv.w;
        }
        #pragma unroll
        for (int o = 16; o; o >>= 1) s += __shfl_xor_sync(0xffffffffu, s, o);
        if (lane == 0) O[m*J + j] = s + bias[j];
    }
}

// ---------------- launch ----------------
extern "C" void kernel_launch(void* const* d_in, const int* in_sizes, int n_in,
                              void* d_out, int out_size){
    const float* x    = (const float*)d_in[0];
    const float* rois = (const float*)d_in[1];
    const float* ow1  = (const float*)d_in[2];
    const float* ob1  = (const float*)d_in[3];
    const float* ow2  = (const float*)d_in[4];
    const float* ob2  = (const float*)d_in[5];
    const float* ow3  = (const float*)d_in[6];
    const float* ob3  = (const float*)d_in[7];
    const float* f1w  = (const float*)d_in[8];
    const float* f1b  = (const float*)d_in[9];
    const float* f2w  = (const float*)d_in[10];
    const float* f2b  = (const float*)d_in[11];
    const float* bxw  = (const float*)d_in[12];
    const float* bxb  = (const float*)d_in[13];

    cudaFuncSetAttribute(gemm_f16<1>, cudaFuncAttributeMaxDynamicSharedMemorySize, 2*2*BM*ROWB);
    cudaFuncSetAttribute(gemm_f16<2>, cudaFuncAttributeMaxDynamicSharedMemorySize, 2*3*BM*ROWB);

    __half *w1f, *w2f, *fw1f, *fw2f, *h1hi, *h1lo, *f1hi, *f1lo;
    cudaGetSymbolAddress((void**)&w1f,  g_w1f);   cudaGetSymbolAddress((void**)&w2f,  g_w2f);
    cudaGetSymbolAddress((void**)&fw1f, g_fw1f);  cudaGetSymbolAddress((void**)&fw2f, g_fw2f);
    cudaGetSymbolAddress((void**)&h1hi, g_h1hi);  cudaGetSymbolAddress((void**)&h1lo, g_h1lo);
    cudaGetSymbolAddress((void**)&f1hi, g_f1hi);  cudaGetSymbolAddress((void**)&f1lo, g_f1lo);
    __half *paf;
    cudaGetSymbolAddress((void**)&paf, g_pa);

    // 1
    nchw2nhwc<<<BIMG*HH*WW, CCH>>>(x);
    // 2
    convw_f16<<<(DFC*KIN/4 + 255)/256, 256>>>(ow1, w1f, DFC*KIN/4);
    // 3
    pool_kernel<<<dim3(N_ROIS,2), 256>>>(rois, 0);
    // 4: h1 = relu(p @ ow1^T + b1)  [256x1024], 392 chunks: SK=28, cpz=14  (ncu capture target)
    gemm_f16<1><<<dim3(8,2,28), 256, 2*2*BM*ROWB>>>(paf, nullptr, w1f, KIN, DFC, 14);
    // 5
    reduce_bias_relu<<<(N_ROIS*DFC/4)/256, 256>>>(0, ob1, N_ROIS*DFC, DFC, 28);
    // 6
    convw_f16<<<(DFC*DFC/4 + 255)/256, 256>>>(ow2, w2f, DFC*DFC/4);
    // 7: h2 = relu(h1 @ ow2^T + b2)  K=1024 (32 chunks): SK=16, cpz=2
    gemm_f16<2><<<dim3(8,2,16), 256, 2*3*BM*ROWB>>>(h1hi, h1lo, w2f, DFC, DFC, 2);
    // 8
    reduce_bias_relu<<<(N_ROIS*DFC/4)/256, 256>>>(1, ob2, N_ROIS*DFC, DFC, 16);
    // 9
    smalldot<<<N_ROIS, 256>>>(0, ow3, ob3, nullptr, DFC, 98);
    // 10
    pool_kernel<<<dim3(N_ROIS,2), 256>>>(rois, 1);
    // 11
    convw_f16<<<(FCC*KIN/4 + 255)/256, 256>>>(f1w, fw1f, FCC*KIN/4);
    // 12: f1 = relu(p @ f1w^T + b)  [256x512], 392 chunks: SK=56, cpz=7
    gemm_f16<1><<<dim3(4,2,56), 256, 2*2*BM*ROWB>>>(paf, nullptr, fw1f, KIN, FCC, 7);
    // 13
    reduce_bias_relu<<<(N_ROIS*FCC/4)/256, 256>>>(2, f1b, N_ROIS*FCC, FCC, 56);
    // 14
    convw_f16<<<(FCC*FCC/4 + 255)/256, 256>>>(f2w, fw2f, FCC*FCC/4);
    // 15: f2 = relu(f1 @ f2w^T + b)  K=512 (16 chunks): SK=16, cpz=1
    gemm_f16<2><<<dim3(4,2,16), 256, 2*3*BM*ROWB>>>(f1hi, f1lo, fw2f, FCC, FCC, 1);
    // 16
    reduce_bias_relu<<<(N_ROIS*FCC/4)/256, 256>>>(3, f2b, N_ROIS*FCC, FCC, 16);
    // 17
    smalldot<<<N_ROIS, 256>>>(1, bxw, bxb, (float*)d_out, FCC, 4);
}